// round 14
// baseline (speedup 1.0000x reference)
#include <cuda_runtime.h>
#include <cuda_bf16.h>
#include <math.h>

// Problem constants
constexpr int B_ = 2, T_ = 2048, E_ = 1024, H_ = 16, FFDIM = 4096, L_ = 4;
constexpr int M_ = B_ * T_;           // 4096 token rows
constexpr int QKVW = 3 * E_;          // 3072

// gemm smem (CTA 64x128, BK=32): As_h(5120) As_l(5120) Bs_h(8704) Bs_l(8704)
constexpr int BUF_B   = 27648;
constexpr int OFF_ASL = 5120;
constexpr int OFF_BSH = 10240;
constexpr int OFF_BSL = 18944;
constexpr int SMEM_G  = 2 * BUF_B;    // 55296 -> 2 CTAs/SM

// attention smem: 3-buffer ring, each 36864 B (Kh|Kl|Vh|Vl, 64x72 shorts each)
constexpr int ABUF    = 36864;
constexpr int SMEM_A  = 3 * ABUF;     // 110592

// Scratch (device globals; no allocations allowed)
__device__ float g_x[M_ * E_];
__device__ float g_attn[M_ * E_];
__device__ float g_h[M_ * FFDIM];
__device__ __nv_bfloat16 g_qkvh[(size_t)M_ * QKVW];
__device__ __nv_bfloat16 g_qkvl[(size_t)M_ * QKVW];

__device__ __forceinline__ float gelu_tanh(float x) {
    float x3 = x * x * x;
    return 0.5f * x * (1.0f + tanhf(0.7978845608028654f * (x + 0.044715f * x3)));
}
__device__ __forceinline__ unsigned pack2(float lo, float hi) {
    unsigned r;
    asm("cvt.rn.bf16x2.f32 %0, %1, %2;" : "=r"(r) : "f"(hi), "f"(lo));
    return r;
}
__device__ __forceinline__ void ldmx4(unsigned* r, unsigned addr) {
    asm volatile("ldmatrix.sync.aligned.m8n8.x4.shared.b16 {%0,%1,%2,%3}, [%4];"
        : "=r"(r[0]), "=r"(r[1]), "=r"(r[2]), "=r"(r[3]) : "r"(addr));
}
__device__ __forceinline__ void ldmx4t(unsigned* r, unsigned addr) {
    asm volatile("ldmatrix.sync.aligned.m8n8.x4.trans.shared.b16 {%0,%1,%2,%3}, [%4];"
        : "=r"(r[0]), "=r"(r[1]), "=r"(r[2]), "=r"(r[3]) : "r"(addr));
}
__device__ __forceinline__ void mma16816(float* d, const unsigned* a, const unsigned* b) {
    asm volatile("mma.sync.aligned.m16n8k16.row.col.f32.bf16.bf16.f32 "
        "{%0,%1,%2,%3}, {%4,%5,%6,%7}, {%8,%9}, {%0,%1,%2,%3};"
        : "+f"(d[0]), "+f"(d[1]), "+f"(d[2]), "+f"(d[3])
        : "r"(a[0]), "r"(a[1]), "r"(a[2]), "r"(a[3]), "r"(b[0]), "r"(b[1]));
}
__device__ __forceinline__ void split4(float4 v, unsigned& h0, unsigned& h1,
                                       unsigned& l0, unsigned& l1) {
    h0 = pack2(v.x, v.y); h1 = pack2(v.z, v.w);
    float rx = __uint_as_float(h0 << 16), ry = __uint_as_float(h0 & 0xFFFF0000u);
    float rz = __uint_as_float(h1 << 16), rw = __uint_as_float(h1 & 0xFFFF0000u);
    l0 = pack2(v.x - rx, v.y - ry); l1 = pack2(v.z - rz, v.w - rw);
}
__device__ __forceinline__ void cpa16(unsigned dst, const void* src) {
    asm volatile("cp.async.cg.shared.global [%0], [%1], 16;" :: "r"(dst), "l"(src) : "memory");
}
__device__ __forceinline__ void cpa_commit() {
    asm volatile("cp.async.commit_group;" ::: "memory");
}
template <int W> __device__ __forceinline__ void cpa_wait() {
    asm volatile("cp.async.wait_group %0;" :: "n"(W) : "memory");
}

// ---------------------------------------------------------------------------
// Tensor-core GEMM, bf16 3-term split, fp32 accum.
// CTA tile 64x128, BK=32, 256 threads (8 warps, 32x32 warp tiles).
// __launch_bounds__(256, 2): TWO CTAs per SM so one CTA's MMAs cover the
// other's barrier/stage/epilogue bubbles (the 60%-plateau mechanism).
// Double-buffered smem, one __syncthreads per K-stage.
// WPL=true: epilogue writes bf16 hi/lo planes instead of fp32.
// ---------------------------------------------------------------------------
template <int ACT, bool RES, bool WPL>
__global__ void __launch_bounds__(256, 2) gemm_mma(
    const float* __restrict__ A, const float* __restrict__ W,
    const float* __restrict__ bias, const float* __restrict__ res,
    float* __restrict__ C, __nv_bfloat16* __restrict__ Ch,
    __nv_bfloat16* __restrict__ Cl, int M, int N, int K)
{
    extern __shared__ char smem[];

    const int bm = blockIdx.y * 64;
    const int bn = blockIdx.x * 128;
    const int tid = threadIdx.x;
    const int lane = tid & 31;
    const int warp = tid >> 5;              // 0..7
    const int wm = (warp >> 2) * 32;        // 2 m-blocks of 32
    const int wn = (warp & 3) * 32;         // 4 n-blocks of 32

    float acc[2][4][4];
#pragma unroll
    for (int i = 0; i < 2; i++)
#pragma unroll
        for (int j = 0; j < 4; j++)
#pragma unroll
            for (int t = 0; t < 4; t++) acc[i][j][t] = 0.0f;

    float4 Ar[2], Br[4];

    auto load_tile = [&](int k0) {
#pragma unroll
        for (int i = 0; i < 2; i++) {
            int f = tid + 256 * i;               // 512: 64 rows x 8 chunks
            int r = f >> 3, kc = (f & 7) << 2;
            Ar[i] = *reinterpret_cast<const float4*>(&A[(size_t)(bm + r) * K + k0 + kc]);
        }
#pragma unroll
        for (int i = 0; i < 4; i++) {
            int f = tid + 256 * i;               // 1024: 32 rows x 32 chunks
            int r = f >> 5, nc = (f & 31) << 2;
            Br[i] = *reinterpret_cast<const float4*>(&W[(size_t)(k0 + r) * N + bn + nc]);
        }
    };

    auto stage_tile = [&](int b) {
        unsigned short* As_h = (unsigned short*)(smem + b * BUF_B);
        unsigned short* As_l = (unsigned short*)(smem + b * BUF_B + OFF_ASL);
        unsigned short* Bs_h = (unsigned short*)(smem + b * BUF_B + OFF_BSH);
        unsigned short* Bs_l = (unsigned short*)(smem + b * BUF_B + OFF_BSL);
#pragma unroll
        for (int i = 0; i < 2; i++) {
            int f = tid + 256 * i;
            int r = f >> 3, kc = (f & 7) << 2;
            unsigned h0, h1, l0, l1;
            split4(Ar[i], h0, h1, l0, l1);
            *reinterpret_cast<uint2*>(&As_h[r * 40 + kc]) = make_uint2(h0, h1);
            *reinterpret_cast<uint2*>(&As_l[r * 40 + kc]) = make_uint2(l0, l1);
        }
#pragma unroll
        for (int i = 0; i < 4; i++) {
            int f = tid + 256 * i;
            int r = f >> 5, nc = (f & 31) << 2;
            unsigned h0, h1, l0, l1;
            split4(Br[i], h0, h1, l0, l1);
            *reinterpret_cast<uint2*>(&Bs_h[r * 136 + nc]) = make_uint2(h0, h1);
            *reinterpret_cast<uint2*>(&Bs_l[r * 136 + nc]) = make_uint2(l0, l1);
        }
    };

    auto compute = [&](int b) {
        unsigned short* As_h = (unsigned short*)(smem + b * BUF_B);
        unsigned short* As_l = (unsigned short*)(smem + b * BUF_B + OFF_ASL);
        unsigned short* Bs_h = (unsigned short*)(smem + b * BUF_B + OFF_BSH);
        unsigned short* Bs_l = (unsigned short*)(smem + b * BUF_B + OFF_BSL);
#pragma unroll
        for (int ks = 0; ks < 32; ks += 16) {
            unsigned bh[2][4], bl[2][4];
#pragma unroll
            for (int g = 0; g < 2; g++) {
                int brow = ks + (lane & 15);
                int bcol = wn + g * 16 + ((lane >> 4) << 3);
                ldmx4t(bh[g], (unsigned)__cvta_generic_to_shared(&Bs_h[brow * 136 + bcol]));
                ldmx4t(bl[g], (unsigned)__cvta_generic_to_shared(&Bs_l[brow * 136 + bcol]));
            }
#pragma unroll
            for (int ma = 0; ma < 2; ma++) {
                int arow = wm + ma * 16 + (lane & 15);
                int acol = ks + ((lane >> 4) << 3);
                unsigned ah[4], al[4];
                ldmx4(ah, (unsigned)__cvta_generic_to_shared(&As_h[arow * 40 + acol]));
                ldmx4(al, (unsigned)__cvta_generic_to_shared(&As_l[arow * 40 + acol]));
#pragma unroll
                for (int na = 0; na < 4; na++) {
                    const unsigned* bhp = &bh[na >> 1][(na & 1) * 2];
                    const unsigned* blp = &bl[na >> 1][(na & 1) * 2];
                    mma16816(acc[ma][na], ah, bhp);
                    mma16816(acc[ma][na], ah, blp);
                    mma16816(acc[ma][na], al, bhp);
                }
            }
        }
    };

    const int S = K >> 5;
    load_tile(0);
    stage_tile(0);
    __syncthreads();

    for (int s = 0; s < S; s++) {
        if (s + 1 < S) load_tile((s + 1) << 5);
        compute(s & 1);
        if (s + 1 < S) {
            stage_tile((s + 1) & 1);
            __syncthreads();
        }
    }

    // Epilogue: bias (+GELU) (+residual); fp32 or hi/lo plane writes
#pragma unroll
    for (int ma = 0; ma < 2; ma++) {
        int r0 = bm + wm + ma * 16 + (lane >> 2);
#pragma unroll
        for (int na = 0; na < 4; na++) {
            int c0 = bn + wn + na * 8 + ((lane & 3) << 1);
            float b0v = bias[c0], b1v = bias[c0 + 1];
            float v00 = acc[ma][na][0] + b0v, v01 = acc[ma][na][1] + b1v;
            float v10 = acc[ma][na][2] + b0v, v11 = acc[ma][na][3] + b1v;
            if (ACT == 1) {
                v00 = gelu_tanh(v00); v01 = gelu_tanh(v01);
                v10 = gelu_tanh(v10); v11 = gelu_tanh(v11);
            }
            if (RES) {
                v00 += res[(size_t)r0 * N + c0];
                v01 += res[(size_t)r0 * N + c0 + 1];
                v10 += res[(size_t)(r0 + 8) * N + c0];
                v11 += res[(size_t)(r0 + 8) * N + c0 + 1];
            }
            if (WPL) {
                unsigned h0 = pack2(v00, v01);
                float rx = __uint_as_float(h0 << 16), ry = __uint_as_float(h0 & 0xFFFF0000u);
                unsigned l0 = pack2(v00 - rx, v01 - ry);
                unsigned h1 = pack2(v10, v11);
                float rz = __uint_as_float(h1 << 16), rw = __uint_as_float(h1 & 0xFFFF0000u);
                unsigned l1 = pack2(v10 - rz, v11 - rw);
                *reinterpret_cast<unsigned*>(&Ch[(size_t)r0 * N + c0]) = h0;
                *reinterpret_cast<unsigned*>(&Cl[(size_t)r0 * N + c0]) = l0;
                *reinterpret_cast<unsigned*>(&Ch[(size_t)(r0 + 8) * N + c0]) = h1;
                *reinterpret_cast<unsigned*>(&Cl[(size_t)(r0 + 8) * N + c0]) = l1;
            } else {
                *reinterpret_cast<float2*>(&C[(size_t)r0 * N + c0]) = make_float2(v00, v01);
                *reinterpret_cast<float2*>(&C[(size_t)(r0 + 8) * N + c0]) = make_float2(v10, v11);
            }
        }
    }
}

// ---------------------------------------------------------------------------
// Tensor-core flash attention (verified round-13 version, unchanged):
// plane inputs, cp.async 3-buffer ring, one sync per kv-tile, 2 CTAs/SM.
// ---------------------------------------------------------------------------
__global__ void __launch_bounds__(256, 2) attn_mma(
    const __nv_bfloat16* __restrict__ qkvh,
    const __nv_bfloat16* __restrict__ qkvl, float* __restrict__ out)
{
    extern __shared__ char asm_[];
    const unsigned sb = (unsigned)__cvta_generic_to_shared(asm_);

    const int b = blockIdx.y >> 4;
    const int h = blockIdx.y & 15;
    const int q0 = blockIdx.x * 128;
    const int tid = threadIdx.x;
    const int lane = tid & 31;
    const int warp = tid >> 5;
    const size_t rowbase = (size_t)b * T_ * QKVW;
    const int hc = h * 64;

#pragma unroll
    for (int i = 0; i < 8; i++) {
        int f = tid + 256 * i;
        int plane = f >> 10;
        int r = (f >> 3) & 127;
        int c = f & 7;
        const __nv_bfloat16* src =
            (plane ? qkvl : qkvh) + rowbase + (size_t)(q0 + r) * QKVW + hc + c * 8;
        cpa16(sb + plane * 18432 + r * 144 + c * 16, src);
    }
    cpa_commit();
    cpa_wait<0>();
    __syncthreads();

    unsigned short* Qh = (unsigned short*)asm_;
    unsigned short* Ql = (unsigned short*)(asm_ + 18432);
    unsigned qh[4][4], ql[4][4];
#pragma unroll
    for (int ks = 0; ks < 4; ks++) {
        int row = warp * 16 + (lane & 15);
        int col = ks * 16 + ((lane >> 4) << 3);
        ldmx4(qh[ks], (unsigned)__cvta_generic_to_shared(&Qh[row * 72 + col]));
        ldmx4(ql[ks], (unsigned)__cvta_generic_to_shared(&Ql[row * 72 + col]));
    }
    __syncthreads();

    float oacc[8][4];
#pragma unroll
    for (int t = 0; t < 8; t++)
#pragma unroll
        for (int j = 0; j < 4; j++) oacc[t][j] = 0.0f;
    float m0 = -1e30f, m1 = -1e30f, lsum0 = 0.0f, lsum1 = 0.0f;

    auto stage_kv = [&](int s) {
        int kt = s * 64;
        unsigned base = sb + (s % 3) * ABUF;
#pragma unroll
        for (int i = 0; i < 8; i++) {
            int f = tid + 256 * i;
            int plane = f >> 9;
            int r = (f >> 3) & 63;
            int c = f & 7;
            int col = ((plane >> 1) ? 2 * E_ : E_) + hc + c * 8;
            const __nv_bfloat16* pl = (plane & 1) ? qkvl : qkvh;
            cpa16(base + plane * 9216 + r * 144 + c * 16,
                  pl + rowbase + (size_t)(kt + r) * QKVW + col);
        }
        cpa_commit();
    };

    stage_kv(0);
    stage_kv(1);

    constexpr int NIT = T_ / 64;
    for (int it = 0; it < NIT; it++) {
        cpa_wait<1>();
        __syncthreads();
        if (it + 2 < NIT) stage_kv(it + 2);

        const int bb = it % 3;
        unsigned short* Kh = (unsigned short*)(asm_ + bb * ABUF);
        unsigned short* Kl = Kh + 4608;
        unsigned short* Vh = Kh + 9216;
        unsigned short* Vl = Kh + 13824;

        float sacc[8][4];
#pragma unroll
        for (int t = 0; t < 8; t++)
#pragma unroll
            for (int j = 0; j < 4; j++) sacc[t][j] = 0.0f;

#pragma unroll
        for (int ks = 0; ks < 4; ks++) {
#pragma unroll
            for (int g = 0; g < 4; g++) {
                int row = g * 16 + ((lane >> 4) << 3) + (lane & 7);
                int col = ks * 16 + (((lane >> 3) & 1) << 3);
                unsigned bh[4], bl[4];
                ldmx4(bh, (unsigned)__cvta_generic_to_shared(&Kh[row * 72 + col]));
                ldmx4(bl, (unsigned)__cvta_generic_to_shared(&Kl[row * 72 + col]));
                mma16816(sacc[2 * g],     qh[ks], &bh[0]);
                mma16816(sacc[2 * g],     qh[ks], &bl[0]);
                mma16816(sacc[2 * g],     ql[ks], &bh[0]);
                mma16816(sacc[2 * g + 1], qh[ks], &bh[2]);
                mma16816(sacc[2 * g + 1], qh[ks], &bl[2]);
                mma16816(sacc[2 * g + 1], ql[ks], &bh[2]);
            }
        }
#pragma unroll
        for (int t = 0; t < 8; t++) {
            sacc[t][0] *= 0.125f; sacc[t][1] *= 0.125f;
            sacc[t][2] *= 0.125f; sacc[t][3] *= 0.125f;
        }

        float mx0 = -1e30f, mx1 = -1e30f;
#pragma unroll
        for (int t = 0; t < 8; t++) {
            mx0 = fmaxf(mx0, fmaxf(sacc[t][0], sacc[t][1]));
            mx1 = fmaxf(mx1, fmaxf(sacc[t][2], sacc[t][3]));
        }
        mx0 = fmaxf(mx0, __shfl_xor_sync(0xffffffffu, mx0, 1));
        mx0 = fmaxf(mx0, __shfl_xor_sync(0xffffffffu, mx0, 2));
        mx1 = fmaxf(mx1, __shfl_xor_sync(0xffffffffu, mx1, 1));
        mx1 = fmaxf(mx1, __shfl_xor_sync(0xffffffffu, mx1, 2));
        float mn0 = fmaxf(m0, mx0), mn1 = fmaxf(m1, mx1);
        float c0 = __expf(m0 - mn0), c1 = __expf(m1 - mn1);
        m0 = mn0; m1 = mn1;
        float s0 = 0.0f, s1 = 0.0f;
#pragma unroll
        for (int t = 0; t < 8; t++) {
            sacc[t][0] = __expf(sacc[t][0] - m0);
            sacc[t][1] = __expf(sacc[t][1] - m0);
            sacc[t][2] = __expf(sacc[t][2] - m1);
            sacc[t][3] = __expf(sacc[t][3] - m1);
            s0 += sacc[t][0] + sacc[t][1];
            s1 += sacc[t][2] + sacc[t][3];
        }
        s0 += __shfl_xor_sync(0xffffffffu, s0, 1);
        s0 += __shfl_xor_sync(0xffffffffu, s0, 2);
        s1 += __shfl_xor_sync(0xffffffffu, s1, 1);
        s1 += __shfl_xor_sync(0xffffffffu, s1, 2);
        lsum0 = lsum0 * c0 + s0;
        lsum1 = lsum1 * c1 + s1;
#pragma unroll
        for (int t = 0; t < 8; t++) {
            oacc[t][0] *= c0; oacc[t][1] *= c0;
            oacc[t][2] *= c1; oacc[t][3] *= c1;
        }

#pragma unroll
        for (int kk = 0; kk < 4; kk++) {
            unsigned ph[4], pl[4];
            ph[0] = pack2(sacc[2 * kk][0], sacc[2 * kk][1]);
            ph[1] = pack2(sacc[2 * kk][2], sacc[2 * kk][3]);
            ph[2] = pack2(sacc[2 * kk + 1][0], sacc[2 * kk + 1][1]);
            ph[3] = pack2(sacc[2 * kk + 1][2], sacc[2 * kk + 1][3]);
#pragma unroll
            for (int u2 = 0; u2 < 4; u2++) {
                const float* p = sacc[2 * kk + (u2 >> 1)];
                int o = (u2 & 1) * 2;
                float rx = __uint_as_float(ph[u2] << 16);
                float ry = __uint_as_float(ph[u2] & 0xFFFF0000u);
                pl[u2] = pack2(p[o] - rx, p[o + 1] - ry);
            }
#pragma unroll
            for (int g = 0; g < 4; g++) {
                int row = kk * 16 + (((lane >> 3) & 1) << 3) + (lane & 7);
                int col = g * 16 + ((lane >> 4) << 3);
                unsigned vh[4], vl[4];
                ldmx4t(vh, (unsigned)__cvta_generic_to_shared(&Vh[row * 72 + col]));
                ldmx4t(vl, (unsigned)__cvta_generic_to_shared(&Vl[row * 72 + col]));
                mma16816(oacc[2 * g],     ph, &vh[0]);
                mma16816(oacc[2 * g],     ph, &vl[0]);
                mma16816(oacc[2 * g],     pl, &vh[0]);
                mma16816(oacc[2 * g + 1], ph, &vh[2]);
                mma16816(oacc[2 * g + 1], ph, &vl[2]);
                mma16816(oacc[2 * g + 1], pl, &vh[2]);
            }
        }
    }

    float inv0 = 1.0f / lsum0, inv1 = 1.0f / lsum1;
    int r0 = q0 + warp * 16 + (lane >> 2);
#pragma unroll
    for (int t = 0; t < 8; t++) {
        int col = hc + t * 8 + ((lane & 3) << 1);
        *reinterpret_cast<float2*>(&out[((size_t)b * T_ + r0) * E_ + col]) =
            make_float2(oacc[t][0] * inv0, oacc[t][1] * inv0);
        *reinterpret_cast<float2*>(&out[((size_t)b * T_ + r0 + 8) * E_ + col]) =
            make_float2(oacc[t][2] * inv1, oacc[t][3] * inv1);
    }
}

// ---------------------------------------------------------------------------
// Orchestration
// ---------------------------------------------------------------------------
extern "C" void kernel_launch(void* const* d_in, const int* in_sizes, int n_in,
                              void* d_out, int out_size)
{
    const float* x_in  = (const float*)d_in[0];
    const float* Wqkv  = (const float*)d_in[1];
    const float* bqkv  = (const float*)d_in[2];
    const float* Wproj = (const float*)d_in[3];
    const float* bproj = (const float*)d_in[4];
    const float* W1    = (const float*)d_in[5];
    const float* b1    = (const float*)d_in[6];
    const float* W2    = (const float*)d_in[7];
    const float* b2    = (const float*)d_in[8];
    float* out = (float*)d_out;

    cudaFuncSetAttribute(gemm_mma<0, false, true>,
                         cudaFuncAttributeMaxDynamicSharedMemorySize, SMEM_G);
    cudaFuncSetAttribute(gemm_mma<0, true, false>,
                         cudaFuncAttributeMaxDynamicSharedMemorySize, SMEM_G);
    cudaFuncSetAttribute(gemm_mma<1, false, false>,
                         cudaFuncAttributeMaxDynamicSharedMemorySize, SMEM_G);
    cudaFuncSetAttribute(attn_mma,
                         cudaFuncAttributeMaxDynamicSharedMemorySize, SMEM_A);

    float *gx, *gattn, *gh;
    __nv_bfloat16 *gqh, *gql;
    cudaGetSymbolAddress((void**)&gx, g_x);
    cudaGetSymbolAddress((void**)&gattn, g_attn);
    cudaGetSymbolAddress((void**)&gh, g_h);
    cudaGetSymbolAddress((void**)&gqh, g_qkvh);
    cudaGetSymbolAddress((void**)&gql, g_qkvl);

    dim3 blk(256);
    for (int l = 0; l < L_; l++) {
        const float* xcur = (l == 0) ? x_in : gx;

        // QKV: writes hi/lo planes for attention
        gemm_mma<0, false, true><<<dim3(QKVW / 128, M_ / 64), blk, SMEM_G>>>(
            xcur, Wqkv + (size_t)l * E_ * QKVW, bqkv + (size_t)l * QKVW,
            nullptr, nullptr, gqh, gql, M_, QKVW, E_);

        attn_mma<<<dim3(T_ / 128, B_ * H_), 256, SMEM_A>>>(gqh, gql, gattn);

        gemm_mma<0, true, false><<<dim3(E_ / 128, M_ / 64), blk, SMEM_G>>>(
            gattn, Wproj + (size_t)l * E_ * E_, bproj + (size_t)l * E_,
            xcur, gx, nullptr, nullptr, M_, E_, E_);

        gemm_mma<1, false, false><<<dim3(FFDIM / 128, M_ / 64), blk, SMEM_G>>>(
            gx, W1 + (size_t)l * E_ * FFDIM, b1 + (size_t)l * FFDIM,
            nullptr, gh, nullptr, nullptr, M_, FFDIM, E_);

        float* dst = (l == L_ - 1) ? out : gx;
        gemm_mma<0, true, false><<<dim3(E_ / 128, M_ / 64), blk, SMEM_G>>>(
            gh, W2 + (size_t)l * FFDIM * E_, b2 + (size_t)l * E_,
            gx, dst, nullptr, nullptr, M_, E_, FFDIM);
    }
}

// round 15
// speedup vs baseline: 1.0136x; 1.0136x over previous
#include <cuda_runtime.h>
#include <cuda_bf16.h>
#include <math.h>

// Problem constants
constexpr int B_ = 2, T_ = 2048, E_ = 1024, H_ = 16, FFDIM = 4096, L_ = 4;
constexpr int M_ = B_ * T_;           // 4096 token rows
constexpr int QKVW = 3 * E_;          // 3072

// gemm smem (R11/R13 verified): per-buffer As_h(18432) As_l(18432) Bs_h(17408) Bs_l(17408)
constexpr int BUF_B   = 71680;
constexpr int OFF_ASL = 18432;
constexpr int OFF_BSH = 36864;
constexpr int OFF_BSL = 54272;
constexpr int SMEM_G  = 2 * BUF_B;    // 143360

// attention smem: 3-buffer ring, each 36864 B (Kh|Kl|Vh|Vl, 64x72 shorts each)
constexpr int ABUF    = 36864;
constexpr int SMEM_A  = 3 * ABUF;     // 110592

// Scratch (device globals; no allocations allowed)
__device__ float g_x[M_ * E_];
__device__ float g_attn[M_ * E_];
__device__ float g_h[M_ * FFDIM];
__device__ __nv_bfloat16 g_qkvh[(size_t)M_ * QKVW];
__device__ __nv_bfloat16 g_qkvl[(size_t)M_ * QKVW];

__device__ __forceinline__ float gelu_tanh(float x) {
    float x3 = x * x * x;
    return 0.5f * x * (1.0f + tanhf(0.7978845608028654f * (x + 0.044715f * x3)));
}
__device__ __forceinline__ unsigned pack2(float lo, float hi) {
    unsigned r;
    asm("cvt.rn.bf16x2.f32 %0, %1, %2;" : "=r"(r) : "f"(hi), "f"(lo));
    return r;
}
__device__ __forceinline__ void ldmx4(unsigned* r, unsigned addr) {
    asm volatile("ldmatrix.sync.aligned.m8n8.x4.shared.b16 {%0,%1,%2,%3}, [%4];"
        : "=r"(r[0]), "=r"(r[1]), "=r"(r[2]), "=r"(r[3]) : "r"(addr));
}
__device__ __forceinline__ void ldmx4t(unsigned* r, unsigned addr) {
    asm volatile("ldmatrix.sync.aligned.m8n8.x4.trans.shared.b16 {%0,%1,%2,%3}, [%4];"
        : "=r"(r[0]), "=r"(r[1]), "=r"(r[2]), "=r"(r[3]) : "r"(addr));
}
__device__ __forceinline__ void mma16816(float* d, const unsigned* a, const unsigned* b) {
    asm volatile("mma.sync.aligned.m16n8k16.row.col.f32.bf16.bf16.f32 "
        "{%0,%1,%2,%3}, {%4,%5,%6,%7}, {%8,%9}, {%0,%1,%2,%3};"
        : "+f"(d[0]), "+f"(d[1]), "+f"(d[2]), "+f"(d[3])
        : "r"(a[0]), "r"(a[1]), "r"(a[2]), "r"(a[3]), "r"(b[0]), "r"(b[1]));
}
__device__ __forceinline__ void split4(float4 v, unsigned& h0, unsigned& h1,
                                       unsigned& l0, unsigned& l1) {
    h0 = pack2(v.x, v.y); h1 = pack2(v.z, v.w);
    float rx = __uint_as_float(h0 << 16), ry = __uint_as_float(h0 & 0xFFFF0000u);
    float rz = __uint_as_float(h1 << 16), rw = __uint_as_float(h1 & 0xFFFF0000u);
    l0 = pack2(v.x - rx, v.y - ry); l1 = pack2(v.z - rz, v.w - rw);
}
__device__ __forceinline__ void cpa16(unsigned dst, const void* src) {
    asm volatile("cp.async.cg.shared.global [%0], [%1], 16;" :: "r"(dst), "l"(src) : "memory");
}
__device__ __forceinline__ void cpa_commit() {
    asm volatile("cp.async.commit_group;" ::: "memory");
}
template <int W> __device__ __forceinline__ void cpa_wait() {
    asm volatile("cp.async.wait_group %0;" :: "n"(W) : "memory");
}

// ---------------------------------------------------------------------------
// Tensor-core GEMM (R13 verified), bf16 3-term split, fp32 accum.
// 128x128 tile, BK=64, 512 threads (16 warps, 32x32 warp tiles),
// double-buffered smem, one __syncthreads per K-stage.
// WPL=true: epilogue writes bf16 hi/lo planes instead of fp32.
// ---------------------------------------------------------------------------
template <int ACT, bool RES, bool WPL>
__global__ void __launch_bounds__(512) gemm_mma(
    const float* __restrict__ A, const float* __restrict__ W,
    const float* __restrict__ bias, const float* __restrict__ res,
    float* __restrict__ C, __nv_bfloat16* __restrict__ Ch,
    __nv_bfloat16* __restrict__ Cl, int M, int N, int K)
{
    extern __shared__ char smem[];

    const int bm = blockIdx.y * 128;
    const int bn = blockIdx.x * 128;
    const int tid = threadIdx.x;
    const int lane = tid & 31;
    const int warp = tid >> 5;
    const int wm = (warp >> 2) * 32;
    const int wn = (warp & 3) * 32;

    float acc[2][4][4];
#pragma unroll
    for (int i = 0; i < 2; i++)
#pragma unroll
        for (int j = 0; j < 4; j++)
#pragma unroll
            for (int t = 0; t < 4; t++) acc[i][j][t] = 0.0f;

    float4 Ar[4], Br[4];

    auto load_tile = [&](int k0) {
#pragma unroll
        for (int i = 0; i < 4; i++) {
            int f = tid + 512 * i;
            int r = f >> 4, kc = (f & 15) << 2;
            Ar[i] = *reinterpret_cast<const float4*>(&A[(size_t)(bm + r) * K + k0 + kc]);
        }
#pragma unroll
        for (int i = 0; i < 4; i++) {
            int f = tid + 512 * i;
            int r = f >> 5, nc = (f & 31) << 2;
            Br[i] = *reinterpret_cast<const float4*>(&W[(size_t)(k0 + r) * N + bn + nc]);
        }
    };

    auto stage_tile = [&](int b) {
        unsigned short* As_h = (unsigned short*)(smem + b * BUF_B);
        unsigned short* As_l = (unsigned short*)(smem + b * BUF_B + OFF_ASL);
        unsigned short* Bs_h = (unsigned short*)(smem + b * BUF_B + OFF_BSH);
        unsigned short* Bs_l = (unsigned short*)(smem + b * BUF_B + OFF_BSL);
#pragma unroll
        for (int i = 0; i < 4; i++) {
            int f = tid + 512 * i;
            int r = f >> 4, kc = (f & 15) << 2;
            unsigned h0, h1, l0, l1;
            split4(Ar[i], h0, h1, l0, l1);
            *reinterpret_cast<uint2*>(&As_h[r * 72 + kc]) = make_uint2(h0, h1);
            *reinterpret_cast<uint2*>(&As_l[r * 72 + kc]) = make_uint2(l0, l1);
        }
#pragma unroll
        for (int i = 0; i < 4; i++) {
            int f = tid + 512 * i;
            int r = f >> 5, nc = (f & 31) << 2;
            unsigned h0, h1, l0, l1;
            split4(Br[i], h0, h1, l0, l1);
            *reinterpret_cast<uint2*>(&Bs_h[r * 136 + nc]) = make_uint2(h0, h1);
            *reinterpret_cast<uint2*>(&Bs_l[r * 136 + nc]) = make_uint2(l0, l1);
        }
    };

    auto compute = [&](int b) {
        unsigned short* As_h = (unsigned short*)(smem + b * BUF_B);
        unsigned short* As_l = (unsigned short*)(smem + b * BUF_B + OFF_ASL);
        unsigned short* Bs_h = (unsigned short*)(smem + b * BUF_B + OFF_BSH);
        unsigned short* Bs_l = (unsigned short*)(smem + b * BUF_B + OFF_BSL);
#pragma unroll
        for (int ks = 0; ks < 64; ks += 16) {
            unsigned bh[2][4], bl[2][4];
#pragma unroll
            for (int g = 0; g < 2; g++) {
                int brow = ks + (lane & 15);
                int bcol = wn + g * 16 + ((lane >> 4) << 3);
                ldmx4t(bh[g], (unsigned)__cvta_generic_to_shared(&Bs_h[brow * 136 + bcol]));
                ldmx4t(bl[g], (unsigned)__cvta_generic_to_shared(&Bs_l[brow * 136 + bcol]));
            }
#pragma unroll
            for (int ma = 0; ma < 2; ma++) {
                int arow = wm + ma * 16 + (lane & 15);
                int acol = ks + ((lane >> 4) << 3);
                unsigned ah[4], al[4];
                ldmx4(ah, (unsigned)__cvta_generic_to_shared(&As_h[arow * 72 + acol]));
                ldmx4(al, (unsigned)__cvta_generic_to_shared(&As_l[arow * 72 + acol]));
#pragma unroll
                for (int na = 0; na < 4; na++) {
                    const unsigned* bhp = &bh[na >> 1][(na & 1) * 2];
                    const unsigned* blp = &bl[na >> 1][(na & 1) * 2];
                    mma16816(acc[ma][na], ah, bhp);
                    mma16816(acc[ma][na], ah, blp);
                    mma16816(acc[ma][na], al, bhp);
                }
            }
        }
    };

    const int S = K >> 6;
    load_tile(0);
    stage_tile(0);
    __syncthreads();

    for (int s = 0; s < S; s++) {
        if (s + 1 < S) load_tile((s + 1) << 6);
        compute(s & 1);
        if (s + 1 < S) {
            stage_tile((s + 1) & 1);
            __syncthreads();
        }
    }

    // Epilogue: bias (+GELU) (+residual); fp32 or hi/lo plane writes
#pragma unroll
    for (int ma = 0; ma < 2; ma++) {
        int r0 = bm + wm + ma * 16 + (lane >> 2);
#pragma unroll
        for (int na = 0; na < 4; na++) {
            int c0 = bn + wn + na * 8 + ((lane & 3) << 1);
            float b0v = bias[c0], b1v = bias[c0 + 1];
            float v00 = acc[ma][na][0] + b0v, v01 = acc[ma][na][1] + b1v;
            float v10 = acc[ma][na][2] + b0v, v11 = acc[ma][na][3] + b1v;
            if (ACT == 1) {
                v00 = gelu_tanh(v00); v01 = gelu_tanh(v01);
                v10 = gelu_tanh(v10); v11 = gelu_tanh(v11);
            }
            if (RES) {
                v00 += res[(size_t)r0 * N + c0];
                v01 += res[(size_t)r0 * N + c0 + 1];
                v10 += res[(size_t)(r0 + 8) * N + c0];
                v11 += res[(size_t)(r0 + 8) * N + c0 + 1];
            }
            if (WPL) {
                unsigned h0 = pack2(v00, v01);
                float rx = __uint_as_float(h0 << 16), ry = __uint_as_float(h0 & 0xFFFF0000u);
                unsigned l0 = pack2(v00 - rx, v01 - ry);
                unsigned h1 = pack2(v10, v11);
                float rz = __uint_as_float(h1 << 16), rw = __uint_as_float(h1 & 0xFFFF0000u);
                unsigned l1 = pack2(v10 - rz, v11 - rw);
                *reinterpret_cast<unsigned*>(&Ch[(size_t)r0 * N + c0]) = h0;
                *reinterpret_cast<unsigned*>(&Cl[(size_t)r0 * N + c0]) = l0;
                *reinterpret_cast<unsigned*>(&Ch[(size_t)(r0 + 8) * N + c0]) = h1;
                *reinterpret_cast<unsigned*>(&Cl[(size_t)(r0 + 8) * N + c0]) = l1;
            } else {
                *reinterpret_cast<float2*>(&C[(size_t)r0 * N + c0]) = make_float2(v00, v01);
                *reinterpret_cast<float2*>(&C[(size_t)(r0 + 8) * N + c0]) = make_float2(v10, v11);
            }
        }
    }
}

// ---------------------------------------------------------------------------
// Tensor-core flash attention (R13 math/structure), WITHOUT the 128-reg cap:
// __launch_bounds__(256) only, so ptxas can allocate ~150+ regs spill-free.
// Plane inputs, cp.async 3-buffer ring, one sync per kv-tile.
// ---------------------------------------------------------------------------
__global__ void __launch_bounds__(256) attn_mma(
    const __nv_bfloat16* __restrict__ qkvh,
    const __nv_bfloat16* __restrict__ qkvl, float* __restrict__ out)
{
    extern __shared__ char asm_[];
    const unsigned sb = (unsigned)__cvta_generic_to_shared(asm_);

    const int b = blockIdx.y >> 4;
    const int h = blockIdx.y & 15;
    const int q0 = blockIdx.x * 128;
    const int tid = threadIdx.x;
    const int lane = tid & 31;
    const int warp = tid >> 5;
    const size_t rowbase = (size_t)b * T_ * QKVW;
    const int hc = h * 64;

#pragma unroll
    for (int i = 0; i < 8; i++) {
        int f = tid + 256 * i;
        int plane = f >> 10;
        int r = (f >> 3) & 127;
        int c = f & 7;
        const __nv_bfloat16* src =
            (plane ? qkvl : qkvh) + rowbase + (size_t)(q0 + r) * QKVW + hc + c * 8;
        cpa16(sb + plane * 18432 + r * 144 + c * 16, src);
    }
    cpa_commit();
    cpa_wait<0>();
    __syncthreads();

    unsigned short* Qh = (unsigned short*)asm_;
    unsigned short* Ql = (unsigned short*)(asm_ + 18432);
    unsigned qh[4][4], ql[4][4];
#pragma unroll
    for (int ks = 0; ks < 4; ks++) {
        int row = warp * 16 + (lane & 15);
        int col = ks * 16 + ((lane >> 4) << 3);
        ldmx4(qh[ks], (unsigned)__cvta_generic_to_shared(&Qh[row * 72 + col]));
        ldmx4(ql[ks], (unsigned)__cvta_generic_to_shared(&Ql[row * 72 + col]));
    }
    __syncthreads();

    float oacc[8][4];
#pragma unroll
    for (int t = 0; t < 8; t++)
#pragma unroll
        for (int j = 0; j < 4; j++) oacc[t][j] = 0.0f;
    float m0 = -1e30f, m1 = -1e30f, lsum0 = 0.0f, lsum1 = 0.0f;

    auto stage_kv = [&](int s) {
        int kt = s * 64;
        unsigned base = sb + (s % 3) * ABUF;
#pragma unroll
        for (int i = 0; i < 8; i++) {
            int f = tid + 256 * i;
            int plane = f >> 9;
            int r = (f >> 3) & 63;
            int c = f & 7;
            int col = ((plane >> 1) ? 2 * E_ : E_) + hc + c * 8;
            const __nv_bfloat16* pl = (plane & 1) ? qkvl : qkvh;
            cpa16(base + plane * 9216 + r * 144 + c * 16,
                  pl + rowbase + (size_t)(kt + r) * QKVW + col);
        }
        cpa_commit();
    };

    stage_kv(0);
    stage_kv(1);

    constexpr int NIT = T_ / 64;
    for (int it = 0; it < NIT; it++) {
        cpa_wait<1>();
        __syncthreads();
        if (it + 2 < NIT) stage_kv(it + 2);

        const int bb = it % 3;
        unsigned short* Kh = (unsigned short*)(asm_ + bb * ABUF);
        unsigned short* Kl = Kh + 4608;
        unsigned short* Vh = Kh + 9216;
        unsigned short* Vl = Kh + 13824;

        float sacc[8][4];
#pragma unroll
        for (int t = 0; t < 8; t++)
#pragma unroll
            for (int j = 0; j < 4; j++) sacc[t][j] = 0.0f;

#pragma unroll
        for (int ks = 0; ks < 4; ks++) {
#pragma unroll
            for (int g = 0; g < 4; g++) {
                int row = g * 16 + ((lane >> 4) << 3) + (lane & 7);
                int col = ks * 16 + (((lane >> 3) & 1) << 3);
                unsigned bh[4], bl[4];
                ldmx4(bh, (unsigned)__cvta_generic_to_shared(&Kh[row * 72 + col]));
                ldmx4(bl, (unsigned)__cvta_generic_to_shared(&Kl[row * 72 + col]));
                mma16816(sacc[2 * g],     qh[ks], &bh[0]);
                mma16816(sacc[2 * g],     qh[ks], &bl[0]);
                mma16816(sacc[2 * g],     ql[ks], &bh[0]);
                mma16816(sacc[2 * g + 1], qh[ks], &bh[2]);
                mma16816(sacc[2 * g + 1], qh[ks], &bl[2]);
                mma16816(sacc[2 * g + 1], ql[ks], &bh[2]);
            }
        }
#pragma unroll
        for (int t = 0; t < 8; t++) {
            sacc[t][0] *= 0.125f; sacc[t][1] *= 0.125f;
            sacc[t][2] *= 0.125f; sacc[t][3] *= 0.125f;
        }

        float mx0 = -1e30f, mx1 = -1e30f;
#pragma unroll
        for (int t = 0; t < 8; t++) {
            mx0 = fmaxf(mx0, fmaxf(sacc[t][0], sacc[t][1]));
            mx1 = fmaxf(mx1, fmaxf(sacc[t][2], sacc[t][3]));
        }
        mx0 = fmaxf(mx0, __shfl_xor_sync(0xffffffffu, mx0, 1));
        mx0 = fmaxf(mx0, __shfl_xor_sync(0xffffffffu, mx0, 2));
        mx1 = fmaxf(mx1, __shfl_xor_sync(0xffffffffu, mx1, 1));
        mx1 = fmaxf(mx1, __shfl_xor_sync(0xffffffffu, mx1, 2));
        float mn0 = fmaxf(m0, mx0), mn1 = fmaxf(m1, mx1);
        float c0 = __expf(m0 - mn0), c1 = __expf(m1 - mn1);
        m0 = mn0; m1 = mn1;
        float s0 = 0.0f, s1 = 0.0f;
#pragma unroll
        for (int t = 0; t < 8; t++) {
            sacc[t][0] = __expf(sacc[t][0] - m0);
            sacc[t][1] = __expf(sacc[t][1] - m0);
            sacc[t][2] = __expf(sacc[t][2] - m1);
            sacc[t][3] = __expf(sacc[t][3] - m1);
            s0 += sacc[t][0] + sacc[t][1];
            s1 += sacc[t][2] + sacc[t][3];
        }
        s0 += __shfl_xor_sync(0xffffffffu, s0, 1);
        s0 += __shfl_xor_sync(0xffffffffu, s0, 2);
        s1 += __shfl_xor_sync(0xffffffffu, s1, 1);
        s1 += __shfl_xor_sync(0xffffffffu, s1, 2);
        lsum0 = lsum0 * c0 + s0;
        lsum1 = lsum1 * c1 + s1;
#pragma unroll
        for (int t = 0; t < 8; t++) {
            oacc[t][0] *= c0; oacc[t][1] *= c0;
            oacc[t][2] *= c1; oacc[t][3] *= c1;
        }

#pragma unroll
        for (int kk = 0; kk < 4; kk++) {
            unsigned ph[4], pl[4];
            ph[0] = pack2(sacc[2 * kk][0], sacc[2 * kk][1]);
            ph[1] = pack2(sacc[2 * kk][2], sacc[2 * kk][3]);
            ph[2] = pack2(sacc[2 * kk + 1][0], sacc[2 * kk + 1][1]);
            ph[3] = pack2(sacc[2 * kk + 1][2], sacc[2 * kk + 1][3]);
#pragma unroll
            for (int u2 = 0; u2 < 4; u2++) {
                const float* p = sacc[2 * kk + (u2 >> 1)];
                int o = (u2 & 1) * 2;
                float rx = __uint_as_float(ph[u2] << 16);
                float ry = __uint_as_float(ph[u2] & 0xFFFF0000u);
                pl[u2] = pack2(p[o] - rx, p[o + 1] - ry);
            }
#pragma unroll
            for (int g = 0; g < 4; g++) {
                int row = kk * 16 + (((lane >> 3) & 1) << 3) + (lane & 7);
                int col = g * 16 + ((lane >> 4) << 3);
                unsigned vh[4], vl[4];
                ldmx4t(vh, (unsigned)__cvta_generic_to_shared(&Vh[row * 72 + col]));
                ldmx4t(vl, (unsigned)__cvta_generic_to_shared(&Vl[row * 72 + col]));
                mma16816(oacc[2 * g],     ph, &vh[0]);
                mma16816(oacc[2 * g],     ph, &vl[0]);
                mma16816(oacc[2 * g],     pl, &vh[0]);
                mma16816(oacc[2 * g + 1], ph, &vh[2]);
                mma16816(oacc[2 * g + 1], ph, &vl[2]);
                mma16816(oacc[2 * g + 1], pl, &vh[2]);
            }
        }
    }

    float inv0 = 1.0f / lsum0, inv1 = 1.0f / lsum1;
    int r0 = q0 + warp * 16 + (lane >> 2);
#pragma unroll
    for (int t = 0; t < 8; t++) {
        int col = hc + t * 8 + ((lane & 3) << 1);
        *reinterpret_cast<float2*>(&out[((size_t)b * T_ + r0) * E_ + col]) =
            make_float2(oacc[t][0] * inv0, oacc[t][1] * inv0);
        *reinterpret_cast<float2*>(&out[((size_t)b * T_ + r0 + 8) * E_ + col]) =
            make_float2(oacc[t][2] * inv1, oacc[t][3] * inv1);
    }
}

// ---------------------------------------------------------------------------
// Orchestration
// ---------------------------------------------------------------------------
extern "C" void kernel_launch(void* const* d_in, const int* in_sizes, int n_in,
                              void* d_out, int out_size)
{
    const float* x_in  = (const float*)d_in[0];
    const float* Wqkv  = (const float*)d_in[1];
    const float* bqkv  = (const float*)d_in[2];
    const float* Wproj = (const float*)d_in[3];
    const float* bproj = (const float*)d_in[4];
    const float* W1    = (const float*)d_in[5];
    const float* b1    = (const float*)d_in[6];
    const float* W2    = (const float*)d_in[7];
    const float* b2    = (const float*)d_in[8];
    float* out = (float*)d_out;

    cudaFuncSetAttribute(gemm_mma<0, false, true>,
                         cudaFuncAttributeMaxDynamicSharedMemorySize, SMEM_G);
    cudaFuncSetAttribute(gemm_mma<0, true, false>,
                         cudaFuncAttributeMaxDynamicSharedMemorySize, SMEM_G);
    cudaFuncSetAttribute(gemm_mma<1, false, false>,
                         cudaFuncAttributeMaxDynamicSharedMemorySize, SMEM_G);
    cudaFuncSetAttribute(attn_mma,
                         cudaFuncAttributeMaxDynamicSharedMemorySize, SMEM_A);

    float *gx, *gattn, *gh;
    __nv_bfloat16 *gqh, *gql;
    cudaGetSymbolAddress((void**)&gx, g_x);
    cudaGetSymbolAddress((void**)&gattn, g_attn);
    cudaGetSymbolAddress((void**)&gh, g_h);
    cudaGetSymbolAddress((void**)&gqh, g_qkvh);
    cudaGetSymbolAddress((void**)&gql, g_qkvl);

    dim3 blk(512);
    for (int l = 0; l < L_; l++) {
        const float* xcur = (l == 0) ? x_in : gx;

        // QKV: writes hi/lo planes for attention
        gemm_mma<0, false, true><<<dim3(QKVW / 128, M_ / 128), blk, SMEM_G>>>(
            xcur, Wqkv + (size_t)l * E_ * QKVW, bqkv + (size_t)l * QKVW,
            nullptr, nullptr, gqh, gql, M_, QKVW, E_);

        attn_mma<<<dim3(T_ / 128, B_ * H_), 256, SMEM_A>>>(gqh, gql, gattn);

        gemm_mma<0, true, false><<<dim3(E_ / 128, M_ / 128), blk, SMEM_G>>>(
            gattn, Wproj + (size_t)l * E_ * E_, bproj + (size_t)l * E_,
            xcur, gx, nullptr, nullptr, M_, E_, E_);

        gemm_mma<1, false, false><<<dim3(FFDIM / 128, M_ / 128), blk, SMEM_G>>>(
            gx, W1 + (size_t)l * E_ * FFDIM, b1 + (size_t)l * FFDIM,
            nullptr, gh, nullptr, nullptr, M_, FFDIM, E_);

        float* dst = (l == L_ - 1) ? out : gx;
        gemm_mma<0, true, false><<<dim3(E_ / 128, M_ / 128), blk, SMEM_G>>>(
            gh, W2 + (size_t)l * FFDIM * E_, b2 + (size_t)l * E_,
            gx, dst, nullptr, nullptr, M_, E_, FFDIM);
    }
}

// round 16
// speedup vs baseline: 1.0363x; 1.0224x over previous
#include <cuda_runtime.h>
#include <cuda_bf16.h>
#include <math.h>

// Problem constants
constexpr int B_ = 2, T_ = 2048, E_ = 1024, H_ = 16, FFDIM = 4096, L_ = 4;
constexpr int M_ = B_ * T_;           // 4096 token rows
constexpr int QKVW = 3 * E_;          // 3072

// gemm smem (R13 verified): per-buffer As_h(18432) As_l(18432) Bs_h(17408) Bs_l(17408)
constexpr int BUF_B   = 71680;
constexpr int OFF_ASL = 18432;
constexpr int OFF_BSH = 36864;
constexpr int OFF_BSL = 54272;
constexpr int SMEM_G  = 2 * BUF_B;    // 143360

// attention smem: Q-lo region (18432) + 2 KV buffers (36864 each)
constexpr int AQLO    = 18432;
constexpr int ABUF    = 36864;
constexpr int SMEM_A  = AQLO + 2 * ABUF;   // 92160 -> 2 CTAs/SM

// Scratch (device globals; no allocations allowed)
__device__ float g_x[M_ * E_];
__device__ float g_attn[M_ * E_];
__device__ float g_h[M_ * FFDIM];
__device__ __nv_bfloat16 g_qkvh[(size_t)M_ * QKVW];
__device__ __nv_bfloat16 g_qkvl[(size_t)M_ * QKVW];

__device__ __forceinline__ float gelu_tanh(float x) {
    float x3 = x * x * x;
    return 0.5f * x * (1.0f + tanhf(0.7978845608028654f * (x + 0.044715f * x3)));
}
__device__ __forceinline__ unsigned pack2(float lo, float hi) {
    unsigned r;
    asm("cvt.rn.bf16x2.f32 %0, %1, %2;" : "=r"(r) : "f"(hi), "f"(lo));
    return r;
}
__device__ __forceinline__ void ldmx4(unsigned* r, unsigned addr) {
    asm volatile("ldmatrix.sync.aligned.m8n8.x4.shared.b16 {%0,%1,%2,%3}, [%4];"
        : "=r"(r[0]), "=r"(r[1]), "=r"(r[2]), "=r"(r[3]) : "r"(addr));
}
__device__ __forceinline__ void ldmx4t(unsigned* r, unsigned addr) {
    asm volatile("ldmatrix.sync.aligned.m8n8.x4.trans.shared.b16 {%0,%1,%2,%3}, [%4];"
        : "=r"(r[0]), "=r"(r[1]), "=r"(r[2]), "=r"(r[3]) : "r"(addr));
}
__device__ __forceinline__ void mma16816(float* d, const unsigned* a, const unsigned* b) {
    asm volatile("mma.sync.aligned.m16n8k16.row.col.f32.bf16.bf16.f32 "
        "{%0,%1,%2,%3}, {%4,%5,%6,%7}, {%8,%9}, {%0,%1,%2,%3};"
        : "+f"(d[0]), "+f"(d[1]), "+f"(d[2]), "+f"(d[3])
        : "r"(a[0]), "r"(a[1]), "r"(a[2]), "r"(a[3]), "r"(b[0]), "r"(b[1]));
}
__device__ __forceinline__ void split4(float4 v, unsigned& h0, unsigned& h1,
                                       unsigned& l0, unsigned& l1) {
    h0 = pack2(v.x, v.y); h1 = pack2(v.z, v.w);
    float rx = __uint_as_float(h0 << 16), ry = __uint_as_float(h0 & 0xFFFF0000u);
    float rz = __uint_as_float(h1 << 16), rw = __uint_as_float(h1 & 0xFFFF0000u);
    l0 = pack2(v.x - rx, v.y - ry); l1 = pack2(v.z - rz, v.w - rw);
}
__device__ __forceinline__ void cpa16(unsigned dst, const void* src) {
    asm volatile("cp.async.cg.shared.global [%0], [%1], 16;" :: "r"(dst), "l"(src) : "memory");
}
__device__ __forceinline__ void cpa_commit() {
    asm volatile("cp.async.commit_group;" ::: "memory");
}
template <int W> __device__ __forceinline__ void cpa_wait() {
    asm volatile("cp.async.wait_group %0;" :: "n"(W) : "memory");
}

// ---------------------------------------------------------------------------
// Tensor-core GEMM (R13 verified), bf16 3-term split, fp32 accum.
// 128x128 tile, BK=64, 512 threads (16 warps, 32x32 warp tiles),
// double-buffered smem, one __syncthreads per K-stage.
// WPL=true: epilogue writes bf16 hi/lo planes instead of fp32.
// ---------------------------------------------------------------------------
template <int ACT, bool RES, bool WPL>
__global__ void __launch_bounds__(512) gemm_mma(
    const float* __restrict__ A, const float* __restrict__ W,
    const float* __restrict__ bias, const float* __restrict__ res,
    float* __restrict__ C, __nv_bfloat16* __restrict__ Ch,
    __nv_bfloat16* __restrict__ Cl, int M, int N, int K)
{
    extern __shared__ char smem[];

    const int bm = blockIdx.y * 128;
    const int bn = blockIdx.x * 128;
    const int tid = threadIdx.x;
    const int lane = tid & 31;
    const int warp = tid >> 5;
    const int wm = (warp >> 2) * 32;
    const int wn = (warp & 3) * 32;

    float acc[2][4][4];
#pragma unroll
    for (int i = 0; i < 2; i++)
#pragma unroll
        for (int j = 0; j < 4; j++)
#pragma unroll
            for (int t = 0; t < 4; t++) acc[i][j][t] = 0.0f;

    float4 Ar[4], Br[4];

    auto load_tile = [&](int k0) {
#pragma unroll
        for (int i = 0; i < 4; i++) {
            int f = tid + 512 * i;
            int r = f >> 4, kc = (f & 15) << 2;
            Ar[i] = *reinterpret_cast<const float4*>(&A[(size_t)(bm + r) * K + k0 + kc]);
        }
#pragma unroll
        for (int i = 0; i < 4; i++) {
            int f = tid + 512 * i;
            int r = f >> 5, nc = (f & 31) << 2;
            Br[i] = *reinterpret_cast<const float4*>(&W[(size_t)(k0 + r) * N + bn + nc]);
        }
    };

    auto stage_tile = [&](int b) {
        unsigned short* As_h = (unsigned short*)(smem + b * BUF_B);
        unsigned short* As_l = (unsigned short*)(smem + b * BUF_B + OFF_ASL);
        unsigned short* Bs_h = (unsigned short*)(smem + b * BUF_B + OFF_BSH);
        unsigned short* Bs_l = (unsigned short*)(smem + b * BUF_B + OFF_BSL);
#pragma unroll
        for (int i = 0; i < 4; i++) {
            int f = tid + 512 * i;
            int r = f >> 4, kc = (f & 15) << 2;
            unsigned h0, h1, l0, l1;
            split4(Ar[i], h0, h1, l0, l1);
            *reinterpret_cast<uint2*>(&As_h[r * 72 + kc]) = make_uint2(h0, h1);
            *reinterpret_cast<uint2*>(&As_l[r * 72 + kc]) = make_uint2(l0, l1);
        }
#pragma unroll
        for (int i = 0; i < 4; i++) {
            int f = tid + 512 * i;
            int r = f >> 5, nc = (f & 31) << 2;
            unsigned h0, h1, l0, l1;
            split4(Br[i], h0, h1, l0, l1);
            *reinterpret_cast<uint2*>(&Bs_h[r * 136 + nc]) = make_uint2(h0, h1);
            *reinterpret_cast<uint2*>(&Bs_l[r * 136 + nc]) = make_uint2(l0, l1);
        }
    };

    auto compute = [&](int b) {
        unsigned short* As_h = (unsigned short*)(smem + b * BUF_B);
        unsigned short* As_l = (unsigned short*)(smem + b * BUF_B + OFF_ASL);
        unsigned short* Bs_h = (unsigned short*)(smem + b * BUF_B + OFF_BSH);
        unsigned short* Bs_l = (unsigned short*)(smem + b * BUF_B + OFF_BSL);
#pragma unroll
        for (int ks = 0; ks < 64; ks += 16) {
            unsigned bh[2][4], bl[2][4];
#pragma unroll
            for (int g = 0; g < 2; g++) {
                int brow = ks + (lane & 15);
                int bcol = wn + g * 16 + ((lane >> 4) << 3);
                ldmx4t(bh[g], (unsigned)__cvta_generic_to_shared(&Bs_h[brow * 136 + bcol]));
                ldmx4t(bl[g], (unsigned)__cvta_generic_to_shared(&Bs_l[brow * 136 + bcol]));
            }
#pragma unroll
            for (int ma = 0; ma < 2; ma++) {
                int arow = wm + ma * 16 + (lane & 15);
                int acol = ks + ((lane >> 4) << 3);
                unsigned ah[4], al[4];
                ldmx4(ah, (unsigned)__cvta_generic_to_shared(&As_h[arow * 72 + acol]));
                ldmx4(al, (unsigned)__cvta_generic_to_shared(&As_l[arow * 72 + acol]));
#pragma unroll
                for (int na = 0; na < 4; na++) {
                    const unsigned* bhp = &bh[na >> 1][(na & 1) * 2];
                    const unsigned* blp = &bl[na >> 1][(na & 1) * 2];
                    mma16816(acc[ma][na], ah, bhp);
                    mma16816(acc[ma][na], ah, blp);
                    mma16816(acc[ma][na], al, bhp);
                }
            }
        }
    };

    const int S = K >> 6;
    load_tile(0);
    stage_tile(0);
    __syncthreads();

    for (int s = 0; s < S; s++) {
        if (s + 1 < S) load_tile((s + 1) << 6);
        compute(s & 1);
        if (s + 1 < S) {
            stage_tile((s + 1) & 1);
            __syncthreads();
        }
    }

    // Epilogue: bias (+GELU) (+residual); fp32 or hi/lo plane writes
#pragma unroll
    for (int ma = 0; ma < 2; ma++) {
        int r0 = bm + wm + ma * 16 + (lane >> 2);
#pragma unroll
        for (int na = 0; na < 4; na++) {
            int c0 = bn + wn + na * 8 + ((lane & 3) << 1);
            float b0v = bias[c0], b1v = bias[c0 + 1];
            float v00 = acc[ma][na][0] + b0v, v01 = acc[ma][na][1] + b1v;
            float v10 = acc[ma][na][2] + b0v, v11 = acc[ma][na][3] + b1v;
            if (ACT == 1) {
                v00 = gelu_tanh(v00); v01 = gelu_tanh(v01);
                v10 = gelu_tanh(v10); v11 = gelu_tanh(v11);
            }
            if (RES) {
                v00 += res[(size_t)r0 * N + c0];
                v01 += res[(size_t)r0 * N + c0 + 1];
                v10 += res[(size_t)(r0 + 8) * N + c0];
                v11 += res[(size_t)(r0 + 8) * N + c0 + 1];
            }
            if (WPL) {
                unsigned h0 = pack2(v00, v01);
                float rx = __uint_as_float(h0 << 16), ry = __uint_as_float(h0 & 0xFFFF0000u);
                unsigned l0 = pack2(v00 - rx, v01 - ry);
                unsigned h1 = pack2(v10, v11);
                float rz = __uint_as_float(h1 << 16), rw = __uint_as_float(h1 & 0xFFFF0000u);
                unsigned l1 = pack2(v10 - rz, v11 - rw);
                *reinterpret_cast<unsigned*>(&Ch[(size_t)r0 * N + c0]) = h0;
                *reinterpret_cast<unsigned*>(&Cl[(size_t)r0 * N + c0]) = l0;
                *reinterpret_cast<unsigned*>(&Ch[(size_t)(r0 + 8) * N + c0]) = h1;
                *reinterpret_cast<unsigned*>(&Cl[(size_t)(r0 + 8) * N + c0]) = l1;
            } else {
                *reinterpret_cast<float2*>(&C[(size_t)r0 * N + c0]) = make_float2(v00, v01);
                *reinterpret_cast<float2*>(&C[(size_t)(r0 + 8) * N + c0]) = make_float2(v10, v11);
            }
        }
    }
}

// ---------------------------------------------------------------------------
// Tensor-core flash attention. R13 math; register-pressure fix:
//  - Q lo-plane fragments live in a dedicated SMEM region (reloaded per ks)
//    instead of 16 registers -> no spill under the 128-reg cap
//  - 2-buffer KV ring (R11-verified pattern), cp.async staged, 2 syncs/tile
//  - __launch_bounds__(256, 2): 2 CTAs/SM (92.2 KB smem each)
// ---------------------------------------------------------------------------
__global__ void __launch_bounds__(256, 2) attn_mma(
    const __nv_bfloat16* __restrict__ qkvh,
    const __nv_bfloat16* __restrict__ qkvl, float* __restrict__ out)
{
    extern __shared__ char asm_[];
    const unsigned sb = (unsigned)__cvta_generic_to_shared(asm_);

    const int b = blockIdx.y >> 4;
    const int h = blockIdx.y & 15;
    const int q0 = blockIdx.x * 128;
    const int tid = threadIdx.x;
    const int lane = tid & 31;
    const int warp = tid >> 5;
    const size_t rowbase = (size_t)b * T_ * QKVW;
    const int hc = h * 64;

    // ---- Q: lo plane -> dedicated region [0, AQLO); hi plane -> kv buf0 ----
#pragma unroll
    for (int i = 0; i < 8; i++) {
        int f = tid + 256 * i;             // 2048 chunks
        int plane = f >> 10;               // 0: hi, 1: lo
        int r = (f >> 3) & 127;
        int c = f & 7;
        const __nv_bfloat16* src =
            (plane ? qkvl : qkvh) + rowbase + (size_t)(q0 + r) * QKVW + hc + c * 8;
        unsigned dst = plane ? (sb + r * 144 + c * 16)             // Q lo region
                             : (sb + AQLO + r * 144 + c * 16);     // kv buf0 temp
        cpa16(dst, src);
    }
    cpa_commit();
    cpa_wait<0>();
    __syncthreads();

    unsigned short* Ql = (unsigned short*)asm_;            // persistent [128][72]
    unsigned short* Qh = (unsigned short*)(asm_ + AQLO);   // temp in kv buf0
    unsigned qh[4][4];
#pragma unroll
    for (int ks = 0; ks < 4; ks++) {
        int row = warp * 16 + (lane & 15);
        int col = ks * 16 + ((lane >> 4) << 3);
        ldmx4(qh[ks], (unsigned)__cvta_generic_to_shared(&Qh[row * 72 + col]));
    }
    __syncthreads();   // qh in regs; kv buf0 free. Ql region persists.

    float oacc[8][4];
#pragma unroll
    for (int t = 0; t < 8; t++)
#pragma unroll
        for (int j = 0; j < 4; j++) oacc[t][j] = 0.0f;
    float m0 = -1e30f, m1 = -1e30f, lsum0 = 0.0f, lsum1 = 0.0f;

    // stage kv tile s into buffer s&1 via cp.async (2048 chunks)
    auto stage_kv = [&](int s) {
        int kt = s * 64;
        unsigned base = sb + AQLO + (s & 1) * ABUF;
#pragma unroll
        for (int i = 0; i < 8; i++) {
            int f = tid + 256 * i;
            int plane = f >> 9;            // 0:Kh 1:Kl 2:Vh 3:Vl
            int r = (f >> 3) & 63;
            int c = f & 7;
            int col = ((plane >> 1) ? 2 * E_ : E_) + hc + c * 8;
            const __nv_bfloat16* pl = (plane & 1) ? qkvl : qkvh;
            cpa16(base + plane * 9216 + r * 144 + c * 16,
                  pl + rowbase + (size_t)(kt + r) * QKVW + col);
        }
        cpa_commit();
    };

    stage_kv(0);
    stage_kv(1);

    constexpr int NIT = T_ / 64;
    for (int it = 0; it < NIT; it++) {
        cpa_wait<1>();
        __syncthreads();                    // buf it&1 ready

        const int bb = it & 1;
        unsigned short* Kh = (unsigned short*)(asm_ + AQLO + bb * ABUF);
        unsigned short* Kl = Kh + 4608;
        unsigned short* Vh = Kh + 9216;
        unsigned short* Vl = Kh + 13824;

        float sacc[8][4];
#pragma unroll
        for (int t = 0; t < 8; t++)
#pragma unroll
            for (int j = 0; j < 4; j++) sacc[t][j] = 0.0f;

#pragma unroll
        for (int ks = 0; ks < 4; ks++) {
            // reload Q lo fragment for this ks from the persistent region
            unsigned qlr[4];
            {
                int row = warp * 16 + (lane & 15);
                int col = ks * 16 + ((lane >> 4) << 3);
                ldmx4(qlr, (unsigned)__cvta_generic_to_shared(&Ql[row * 72 + col]));
            }
#pragma unroll
            for (int g = 0; g < 4; g++) {
                int row = g * 16 + ((lane >> 4) << 3) + (lane & 7);
                int col = ks * 16 + (((lane >> 3) & 1) << 3);
                unsigned bh[4], bl[4];
                ldmx4(bh, (unsigned)__cvta_generic_to_shared(&Kh[row * 72 + col]));
                ldmx4(bl, (unsigned)__cvta_generic_to_shared(&Kl[row * 72 + col]));
                mma16816(sacc[2 * g],     qh[ks], &bh[0]);
                mma16816(sacc[2 * g],     qh[ks], &bl[0]);
                mma16816(sacc[2 * g],     qlr,    &bh[0]);
                mma16816(sacc[2 * g + 1], qh[ks], &bh[2]);
                mma16816(sacc[2 * g + 1], qh[ks], &bl[2]);
                mma16816(sacc[2 * g + 1], qlr,    &bh[2]);
            }
        }
#pragma unroll
        for (int t = 0; t < 8; t++) {
            sacc[t][0] *= 0.125f; sacc[t][1] *= 0.125f;
            sacc[t][2] *= 0.125f; sacc[t][3] *= 0.125f;
        }

        float mx0 = -1e30f, mx1 = -1e30f;
#pragma unroll
        for (int t = 0; t < 8; t++) {
            mx0 = fmaxf(mx0, fmaxf(sacc[t][0], sacc[t][1]));
            mx1 = fmaxf(mx1, fmaxf(sacc[t][2], sacc[t][3]));
        }
        mx0 = fmaxf(mx0, __shfl_xor_sync(0xffffffffu, mx0, 1));
        mx0 = fmaxf(mx0, __shfl_xor_sync(0xffffffffu, mx0, 2));
        mx1 = fmaxf(mx1, __shfl_xor_sync(0xffffffffu, mx1, 1));
        mx1 = fmaxf(mx1, __shfl_xor_sync(0xffffffffu, mx1, 2));
        float mn0 = fmaxf(m0, mx0), mn1 = fmaxf(m1, mx1);
        float c0 = __expf(m0 - mn0), c1 = __expf(m1 - mn1);
        m0 = mn0; m1 = mn1;
        float s0 = 0.0f, s1 = 0.0f;
#pragma unroll
        for (int t = 0; t < 8; t++) {
            sacc[t][0] = __expf(sacc[t][0] - m0);
            sacc[t][1] = __expf(sacc[t][1] - m0);
            sacc[t][2] = __expf(sacc[t][2] - m1);
            sacc[t][3] = __expf(sacc[t][3] - m1);
            s0 += sacc[t][0] + sacc[t][1];
            s1 += sacc[t][2] + sacc[t][3];
        }
        s0 += __shfl_xor_sync(0xffffffffu, s0, 1);
        s0 += __shfl_xor_sync(0xffffffffu, s0, 2);
        s1 += __shfl_xor_sync(0xffffffffu, s1, 1);
        s1 += __shfl_xor_sync(0xffffffffu, s1, 2);
        lsum0 = lsum0 * c0 + s0;
        lsum1 = lsum1 * c1 + s1;
#pragma unroll
        for (int t = 0; t < 8; t++) {
            oacc[t][0] *= c0; oacc[t][1] *= c0;
            oacc[t][2] *= c1; oacc[t][3] *= c1;
        }

#pragma unroll
        for (int kk = 0; kk < 4; kk++) {
            unsigned ph[4], pl[4];
            ph[0] = pack2(sacc[2 * kk][0], sacc[2 * kk][1]);
            ph[1] = pack2(sacc[2 * kk][2], sacc[2 * kk][3]);
            ph[2] = pack2(sacc[2 * kk + 1][0], sacc[2 * kk + 1][1]);
            ph[3] = pack2(sacc[2 * kk + 1][2], sacc[2 * kk + 1][3]);
#pragma unroll
            for (int u2 = 0; u2 < 4; u2++) {
                const float* p = sacc[2 * kk + (u2 >> 1)];
                int o = (u2 & 1) * 2;
                float rx = __uint_as_float(ph[u2] << 16);
                float ry = __uint_as_float(ph[u2] & 0xFFFF0000u);
                pl[u2] = pack2(p[o] - rx, p[o + 1] - ry);
            }
#pragma unroll
            for (int g = 0; g < 4; g++) {
                int row = kk * 16 + (((lane >> 3) & 1) << 3) + (lane & 7);
                int col = g * 16 + ((lane >> 4) << 3);
                unsigned vh[4], vl[4];
                ldmx4t(vh, (unsigned)__cvta_generic_to_shared(&Vh[row * 72 + col]));
                ldmx4t(vl, (unsigned)__cvta_generic_to_shared(&Vl[row * 72 + col]));
                mma16816(oacc[2 * g],     ph, &vh[0]);
                mma16816(oacc[2 * g],     ph, &vl[0]);
                mma16816(oacc[2 * g],     pl, &vh[0]);
                mma16816(oacc[2 * g + 1], ph, &vh[2]);
                mma16816(oacc[2 * g + 1], ph, &vl[2]);
                mma16816(oacc[2 * g + 1], pl, &vh[2]);
            }
        }

        if (it + 2 < NIT) {
            __syncthreads();                // all done reading buf it&1
            stage_kv(it + 2);               // overwrite buf it&1
        }
    }

    float inv0 = 1.0f / lsum0, inv1 = 1.0f / lsum1;
    int r0 = q0 + warp * 16 + (lane >> 2);
#pragma unroll
    for (int t = 0; t < 8; t++) {
        int col = hc + t * 8 + ((lane & 3) << 1);
        *reinterpret_cast<float2*>(&out[((size_t)b * T_ + r0) * E_ + col]) =
            make_float2(oacc[t][0] * inv0, oacc[t][1] * inv0);
        *reinterpret_cast<float2*>(&out[((size_t)b * T_ + r0 + 8) * E_ + col]) =
            make_float2(oacc[t][2] * inv1, oacc[t][3] * inv1);
    }
}

// ---------------------------------------------------------------------------
// Orchestration (R13 structure)
// ---------------------------------------------------------------------------
extern "C" void kernel_launch(void* const* d_in, const int* in_sizes, int n_in,
                              void* d_out, int out_size)
{
    const float* x_in  = (const float*)d_in[0];
    const float* Wqkv  = (const float*)d_in[1];
    const float* bqkv  = (const float*)d_in[2];
    const float* Wproj = (const float*)d_in[3];
    const float* bproj = (const float*)d_in[4];
    const float* W1    = (const float*)d_in[5];
    const float* b1    = (const float*)d_in[6];
    const float* W2    = (const float*)d_in[7];
    const float* b2    = (const float*)d_in[8];
    float* out = (float*)d_out;

    cudaFuncSetAttribute(gemm_mma<0, false, true>,
                         cudaFuncAttributeMaxDynamicSharedMemorySize, SMEM_G);
    cudaFuncSetAttribute(gemm_mma<0, true, false>,
                         cudaFuncAttributeMaxDynamicSharedMemorySize, SMEM_G);
    cudaFuncSetAttribute(gemm_mma<1, false, false>,
                         cudaFuncAttributeMaxDynamicSharedMemorySize, SMEM_G);
    cudaFuncSetAttribute(attn_mma,
                         cudaFuncAttributeMaxDynamicSharedMemorySize, SMEM_A);

    float *gx, *gattn, *gh;
    __nv_bfloat16 *gqh, *gql;
    cudaGetSymbolAddress((void**)&gx, g_x);
    cudaGetSymbolAddress((void**)&gattn, g_attn);
    cudaGetSymbolAddress((void**)&gh, g_h);
    cudaGetSymbolAddress((void**)&gqh, g_qkvh);
    cudaGetSymbolAddress((void**)&gql, g_qkvl);

    dim3 blk(512);
    for (int l = 0; l < L_; l++) {
        const float* xcur = (l == 0) ? x_in : gx;

        // QKV: writes hi/lo planes for attention
        gemm_mma<0, false, true><<<dim3(QKVW / 128, M_ / 128), blk, SMEM_G>>>(
            xcur, Wqkv + (size_t)l * E_ * QKVW, bqkv + (size_t)l * QKVW,
            nullptr, nullptr, gqh, gql, M_, QKVW, E_);

        attn_mma<<<dim3(T_ / 128, B_ * H_), 256, SMEM_A>>>(gqh, gql, gattn);

        gemm_mma<0, true, false><<<dim3(E_ / 128, M_ / 128), blk, SMEM_G>>>(
            gattn, Wproj + (size_t)l * E_ * E_, bproj + (size_t)l * E_,
            xcur, gx, nullptr, nullptr, M_, E_, E_);

        gemm_mma<1, false, false><<<dim3(FFDIM / 128, M_ / 128), blk, SMEM_G>>>(
            gx, W1 + (size_t)l * E_ * FFDIM, b1 + (size_t)l * FFDIM,
            nullptr, gh, nullptr, nullptr, M_, FFDIM, E_);

        float* dst = (l == L_ - 1) ? out : gx;
        gemm_mma<0, true, false><<<dim3(E_ / 128, M_ / 128), blk, SMEM_G>>>(
            gh, W2 + (size_t)l * FFDIM * E_, b2 + (size_t)l * E_,
            gx, dst, nullptr, nullptr, M_, E_, FFDIM);
    }
}

// round 17
// speedup vs baseline: 1.1528x; 1.1125x over previous
#include <cuda_runtime.h>
#include <cuda_bf16.h>
#include <cuda_fp16.h>
#include <math.h>

// Problem constants
constexpr int B_ = 2, T_ = 2048, E_ = 1024, H_ = 16, FFDIM = 4096, L_ = 4;
constexpr int M_ = B_ * T_;           // 4096 token rows
constexpr int QKVW = 3 * E_;          // 3072

// bf16 gemm smem (R16 verified): As_h(18432) As_l(18432) Bs_h(17408) Bs_l(17408)
constexpr int BUF_B   = 71680;
constexpr int OFF_ASL = 18432;
constexpr int OFF_BSH = 36864;
constexpr int OFF_BSL = 54272;
constexpr int SMEM_G  = 2 * BUF_B;    // 143360

// fp16 2-term gemm smem: As_h(18432) As_l(18432) Bs_h(17408)  (no B-lo plane)
constexpr int FBUF    = 54272;
constexpr int F_ASL   = 18432;
constexpr int F_BSH   = 36864;
constexpr int SMEM_F  = 2 * FBUF;     // 108544

// attention smem (R16 verified): Q-lo region + 2 KV buffers
constexpr int AQLO    = 18432;
constexpr int ABUF    = 36864;
constexpr int SMEM_A  = AQLO + 2 * ABUF;   // 92160 -> 2 CTAs/SM

// Scratch (device globals; no allocations allowed)
__device__ float g_x[M_ * E_];
__device__ float g_attn[M_ * E_];
__device__ float g_h[M_ * FFDIM];
__device__ __nv_bfloat16 g_qkvh[(size_t)M_ * QKVW];
__device__ __nv_bfloat16 g_qkvl[(size_t)M_ * QKVW];

__device__ __forceinline__ float gelu_tanh(float x) {
    float x3 = x * x * x;
    return 0.5f * x * (1.0f + tanhf(0.7978845608028654f * (x + 0.044715f * x3)));
}
__device__ __forceinline__ unsigned pack2(float lo, float hi) {
    unsigned r;
    asm("cvt.rn.bf16x2.f32 %0, %1, %2;" : "=r"(r) : "f"(hi), "f"(lo));
    return r;
}
__device__ __forceinline__ void ldmx4(unsigned* r, unsigned addr) {
    asm volatile("ldmatrix.sync.aligned.m8n8.x4.shared.b16 {%0,%1,%2,%3}, [%4];"
        : "=r"(r[0]), "=r"(r[1]), "=r"(r[2]), "=r"(r[3]) : "r"(addr));
}
__device__ __forceinline__ void ldmx4t(unsigned* r, unsigned addr) {
    asm volatile("ldmatrix.sync.aligned.m8n8.x4.trans.shared.b16 {%0,%1,%2,%3}, [%4];"
        : "=r"(r[0]), "=r"(r[1]), "=r"(r[2]), "=r"(r[3]) : "r"(addr));
}
__device__ __forceinline__ void mma16816(float* d, const unsigned* a, const unsigned* b) {
    asm volatile("mma.sync.aligned.m16n8k16.row.col.f32.bf16.bf16.f32 "
        "{%0,%1,%2,%3}, {%4,%5,%6,%7}, {%8,%9}, {%0,%1,%2,%3};"
        : "+f"(d[0]), "+f"(d[1]), "+f"(d[2]), "+f"(d[3])
        : "r"(a[0]), "r"(a[1]), "r"(a[2]), "r"(a[3]), "r"(b[0]), "r"(b[1]));
}
__device__ __forceinline__ void mma16816h(float* d, const unsigned* a, const unsigned* b) {
    asm volatile("mma.sync.aligned.m16n8k16.row.col.f32.f16.f16.f32 "
        "{%0,%1,%2,%3}, {%4,%5,%6,%7}, {%8,%9}, {%0,%1,%2,%3};"
        : "+f"(d[0]), "+f"(d[1]), "+f"(d[2]), "+f"(d[3])
        : "r"(a[0]), "r"(a[1]), "r"(a[2]), "r"(a[3]), "r"(b[0]), "r"(b[1]));
}
__device__ __forceinline__ void split4(float4 v, unsigned& h0, unsigned& h1,
                                       unsigned& l0, unsigned& l1) {
    h0 = pack2(v.x, v.y); h1 = pack2(v.z, v.w);
    float rx = __uint_as_float(h0 << 16), ry = __uint_as_float(h0 & 0xFFFF0000u);
    float rz = __uint_as_float(h1 << 16), rw = __uint_as_float(h1 & 0xFFFF0000u);
    l0 = pack2(v.x - rx, v.y - ry); l1 = pack2(v.z - rz, v.w - rw);
}
// fp16 split: a = hi + lo with hi = f16(a), lo = f16(a - hi)
__device__ __forceinline__ void split4h(float4 v, unsigned& h0, unsigned& h1,
                                        unsigned& l0, unsigned& l1) {
    __half2 p0 = __float22half2_rn(make_float2(v.x, v.y));
    __half2 p1 = __float22half2_rn(make_float2(v.z, v.w));
    float2 f0 = __half22float2(p0), f1 = __half22float2(p1);
    __half2 q0 = __float22half2_rn(make_float2(v.x - f0.x, v.y - f0.y));
    __half2 q1 = __float22half2_rn(make_float2(v.z - f1.x, v.w - f1.y));
    h0 = *reinterpret_cast<unsigned*>(&p0); h1 = *reinterpret_cast<unsigned*>(&p1);
    l0 = *reinterpret_cast<unsigned*>(&q0); l1 = *reinterpret_cast<unsigned*>(&q1);
}
__device__ __forceinline__ void cvt4h(float4 v, unsigned& h0, unsigned& h1) {
    __half2 p0 = __float22half2_rn(make_float2(v.x, v.y));
    __half2 p1 = __float22half2_rn(make_float2(v.z, v.w));
    h0 = *reinterpret_cast<unsigned*>(&p0); h1 = *reinterpret_cast<unsigned*>(&p1);
}
__device__ __forceinline__ void cpa16(unsigned dst, const void* src) {
    asm volatile("cp.async.cg.shared.global [%0], [%1], 16;" :: "r"(dst), "l"(src) : "memory");
}
__device__ __forceinline__ void cpa_commit() {
    asm volatile("cp.async.commit_group;" ::: "memory");
}
template <int W> __device__ __forceinline__ void cpa_wait() {
    asm volatile("cp.async.wait_group %0;" :: "n"(W) : "memory");
}

// ---------------------------------------------------------------------------
// bf16 3-term GEMM (R16 verified; used for QKV and proj).
// ---------------------------------------------------------------------------
template <int ACT, bool RES, bool WPL>
__global__ void __launch_bounds__(512) gemm_mma(
    const float* __restrict__ A, const float* __restrict__ W,
    const float* __restrict__ bias, const float* __restrict__ res,
    float* __restrict__ C, __nv_bfloat16* __restrict__ Ch,
    __nv_bfloat16* __restrict__ Cl, int M, int N, int K)
{
    extern __shared__ char smem[];

    const int bm = blockIdx.y * 128;
    const int bn = blockIdx.x * 128;
    const int tid = threadIdx.x;
    const int lane = tid & 31;
    const int warp = tid >> 5;
    const int wm = (warp >> 2) * 32;
    const int wn = (warp & 3) * 32;

    float acc[2][4][4];
#pragma unroll
    for (int i = 0; i < 2; i++)
#pragma unroll
        for (int j = 0; j < 4; j++)
#pragma unroll
            for (int t = 0; t < 4; t++) acc[i][j][t] = 0.0f;

    float4 Ar[4], Br[4];

    auto load_tile = [&](int k0) {
#pragma unroll
        for (int i = 0; i < 4; i++) {
            int f = tid + 512 * i;
            int r = f >> 4, kc = (f & 15) << 2;
            Ar[i] = *reinterpret_cast<const float4*>(&A[(size_t)(bm + r) * K + k0 + kc]);
        }
#pragma unroll
        for (int i = 0; i < 4; i++) {
            int f = tid + 512 * i;
            int r = f >> 5, nc = (f & 31) << 2;
            Br[i] = *reinterpret_cast<const float4*>(&W[(size_t)(k0 + r) * N + bn + nc]);
        }
    };

    auto stage_tile = [&](int b) {
        unsigned short* As_h = (unsigned short*)(smem + b * BUF_B);
        unsigned short* As_l = (unsigned short*)(smem + b * BUF_B + OFF_ASL);
        unsigned short* Bs_h = (unsigned short*)(smem + b * BUF_B + OFF_BSH);
        unsigned short* Bs_l = (unsigned short*)(smem + b * BUF_B + OFF_BSL);
#pragma unroll
        for (int i = 0; i < 4; i++) {
            int f = tid + 512 * i;
            int r = f >> 4, kc = (f & 15) << 2;
            unsigned h0, h1, l0, l1;
            split4(Ar[i], h0, h1, l0, l1);
            *reinterpret_cast<uint2*>(&As_h[r * 72 + kc]) = make_uint2(h0, h1);
            *reinterpret_cast<uint2*>(&As_l[r * 72 + kc]) = make_uint2(l0, l1);
        }
#pragma unroll
        for (int i = 0; i < 4; i++) {
            int f = tid + 512 * i;
            int r = f >> 5, nc = (f & 31) << 2;
            unsigned h0, h1, l0, l1;
            split4(Br[i], h0, h1, l0, l1);
            *reinterpret_cast<uint2*>(&Bs_h[r * 136 + nc]) = make_uint2(h0, h1);
            *reinterpret_cast<uint2*>(&Bs_l[r * 136 + nc]) = make_uint2(l0, l1);
        }
    };

    auto compute = [&](int b) {
        unsigned short* As_h = (unsigned short*)(smem + b * BUF_B);
        unsigned short* As_l = (unsigned short*)(smem + b * BUF_B + OFF_ASL);
        unsigned short* Bs_h = (unsigned short*)(smem + b * BUF_B + OFF_BSH);
        unsigned short* Bs_l = (unsigned short*)(smem + b * BUF_B + OFF_BSL);
#pragma unroll
        for (int ks = 0; ks < 64; ks += 16) {
            unsigned bh[2][4], bl[2][4];
#pragma unroll
            for (int g = 0; g < 2; g++) {
                int brow = ks + (lane & 15);
                int bcol = wn + g * 16 + ((lane >> 4) << 3);
                ldmx4t(bh[g], (unsigned)__cvta_generic_to_shared(&Bs_h[brow * 136 + bcol]));
                ldmx4t(bl[g], (unsigned)__cvta_generic_to_shared(&Bs_l[brow * 136 + bcol]));
            }
#pragma unroll
            for (int ma = 0; ma < 2; ma++) {
                int arow = wm + ma * 16 + (lane & 15);
                int acol = ks + ((lane >> 4) << 3);
                unsigned ah[4], al[4];
                ldmx4(ah, (unsigned)__cvta_generic_to_shared(&As_h[arow * 72 + acol]));
                ldmx4(al, (unsigned)__cvta_generic_to_shared(&As_l[arow * 72 + acol]));
#pragma unroll
                for (int na = 0; na < 4; na++) {
                    const unsigned* bhp = &bh[na >> 1][(na & 1) * 2];
                    const unsigned* blp = &bl[na >> 1][(na & 1) * 2];
                    mma16816(acc[ma][na], ah, bhp);
                    mma16816(acc[ma][na], ah, blp);
                    mma16816(acc[ma][na], al, bhp);
                }
            }
        }
    };

    const int S = K >> 6;
    load_tile(0);
    stage_tile(0);
    __syncthreads();

    for (int s = 0; s < S; s++) {
        if (s + 1 < S) load_tile((s + 1) << 6);
        compute(s & 1);
        if (s + 1 < S) {
            stage_tile((s + 1) & 1);
            __syncthreads();
        }
    }

#pragma unroll
    for (int ma = 0; ma < 2; ma++) {
        int r0 = bm + wm + ma * 16 + (lane >> 2);
#pragma unroll
        for (int na = 0; na < 4; na++) {
            int c0 = bn + wn + na * 8 + ((lane & 3) << 1);
            float b0v = bias[c0], b1v = bias[c0 + 1];
            float v00 = acc[ma][na][0] + b0v, v01 = acc[ma][na][1] + b1v;
            float v10 = acc[ma][na][2] + b0v, v11 = acc[ma][na][3] + b1v;
            if (ACT == 1) {
                v00 = gelu_tanh(v00); v01 = gelu_tanh(v01);
                v10 = gelu_tanh(v10); v11 = gelu_tanh(v11);
            }
            if (RES) {
                v00 += res[(size_t)r0 * N + c0];
                v01 += res[(size_t)r0 * N + c0 + 1];
                v10 += res[(size_t)(r0 + 8) * N + c0];
                v11 += res[(size_t)(r0 + 8) * N + c0 + 1];
            }
            if (WPL) {
                unsigned h0 = pack2(v00, v01);
                float rx = __uint_as_float(h0 << 16), ry = __uint_as_float(h0 & 0xFFFF0000u);
                unsigned l0 = pack2(v00 - rx, v01 - ry);
                unsigned h1 = pack2(v10, v11);
                float rz = __uint_as_float(h1 << 16), rw = __uint_as_float(h1 & 0xFFFF0000u);
                unsigned l1 = pack2(v10 - rz, v11 - rw);
                *reinterpret_cast<unsigned*>(&Ch[(size_t)r0 * N + c0]) = h0;
                *reinterpret_cast<unsigned*>(&Cl[(size_t)r0 * N + c0]) = l0;
                *reinterpret_cast<unsigned*>(&Ch[(size_t)(r0 + 8) * N + c0]) = h1;
                *reinterpret_cast<unsigned*>(&Cl[(size_t)(r0 + 8) * N + c0]) = l1;
            } else {
                *reinterpret_cast<float2*>(&C[(size_t)r0 * N + c0]) = make_float2(v00, v01);
                *reinterpret_cast<float2*>(&C[(size_t)(r0 + 8) * N + c0]) = make_float2(v10, v11);
            }
        }
    }
}

// ---------------------------------------------------------------------------
// fp16 2-term GEMM (MLP only): A split fp16 hi/lo, B single fp16 plane.
// (ah+al)@bh = A@f16(B); dropped term A@(B-f16(B)) ~ 2.8e-4 rms relative.
// 64 MMAs/stage instead of 96. Same tile/pipeline as gemm_mma.
// ---------------------------------------------------------------------------
template <int ACT, bool RES>
__global__ void __launch_bounds__(512) gemm_f16(
    const float* __restrict__ A, const float* __restrict__ W,
    const float* __restrict__ bias, const float* __restrict__ res,
    float* __restrict__ C, int M, int N, int K)
{
    extern __shared__ char smem[];

    const int bm = blockIdx.y * 128;
    const int bn = blockIdx.x * 128;
    const int tid = threadIdx.x;
    const int lane = tid & 31;
    const int warp = tid >> 5;
    const int wm = (warp >> 2) * 32;
    const int wn = (warp & 3) * 32;

    float acc[2][4][4];
#pragma unroll
    for (int i = 0; i < 2; i++)
#pragma unroll
        for (int j = 0; j < 4; j++)
#pragma unroll
            for (int t = 0; t < 4; t++) acc[i][j][t] = 0.0f;

    float4 Ar[4], Br[4];

    auto load_tile = [&](int k0) {
#pragma unroll
        for (int i = 0; i < 4; i++) {
            int f = tid + 512 * i;
            int r = f >> 4, kc = (f & 15) << 2;
            Ar[i] = *reinterpret_cast<const float4*>(&A[(size_t)(bm + r) * K + k0 + kc]);
        }
#pragma unroll
        for (int i = 0; i < 4; i++) {
            int f = tid + 512 * i;
            int r = f >> 5, nc = (f & 31) << 2;
            Br[i] = *reinterpret_cast<const float4*>(&W[(size_t)(k0 + r) * N + bn + nc]);
        }
    };

    auto stage_tile = [&](int b) {
        unsigned short* As_h = (unsigned short*)(smem + b * FBUF);
        unsigned short* As_l = (unsigned short*)(smem + b * FBUF + F_ASL);
        unsigned short* Bs_h = (unsigned short*)(smem + b * FBUF + F_BSH);
#pragma unroll
        for (int i = 0; i < 4; i++) {
            int f = tid + 512 * i;
            int r = f >> 4, kc = (f & 15) << 2;
            unsigned h0, h1, l0, l1;
            split4h(Ar[i], h0, h1, l0, l1);
            *reinterpret_cast<uint2*>(&As_h[r * 72 + kc]) = make_uint2(h0, h1);
            *reinterpret_cast<uint2*>(&As_l[r * 72 + kc]) = make_uint2(l0, l1);
        }
#pragma unroll
        for (int i = 0; i < 4; i++) {
            int f = tid + 512 * i;
            int r = f >> 5, nc = (f & 31) << 2;
            unsigned h0, h1;
            cvt4h(Br[i], h0, h1);
            *reinterpret_cast<uint2*>(&Bs_h[r * 136 + nc]) = make_uint2(h0, h1);
        }
    };

    auto compute = [&](int b) {
        unsigned short* As_h = (unsigned short*)(smem + b * FBUF);
        unsigned short* As_l = (unsigned short*)(smem + b * FBUF + F_ASL);
        unsigned short* Bs_h = (unsigned short*)(smem + b * FBUF + F_BSH);
#pragma unroll
        for (int ks = 0; ks < 64; ks += 16) {
            unsigned bh[2][4];
#pragma unroll
            for (int g = 0; g < 2; g++) {
                int brow = ks + (lane & 15);
                int bcol = wn + g * 16 + ((lane >> 4) << 3);
                ldmx4t(bh[g], (unsigned)__cvta_generic_to_shared(&Bs_h[brow * 136 + bcol]));
            }
#pragma unroll
            for (int ma = 0; ma < 2; ma++) {
                int arow = wm + ma * 16 + (lane & 15);
                int acol = ks + ((lane >> 4) << 3);
                unsigned ah[4], al[4];
                ldmx4(ah, (unsigned)__cvta_generic_to_shared(&As_h[arow * 72 + acol]));
                ldmx4(al, (unsigned)__cvta_generic_to_shared(&As_l[arow * 72 + acol]));
#pragma unroll
                for (int na = 0; na < 4; na++) {
                    const unsigned* bhp = &bh[na >> 1][(na & 1) * 2];
                    mma16816h(acc[ma][na], ah, bhp);
                    mma16816h(acc[ma][na], al, bhp);
                }
            }
        }
    };

    const int S = K >> 6;
    load_tile(0);
    stage_tile(0);
    __syncthreads();

    for (int s = 0; s < S; s++) {
        if (s + 1 < S) load_tile((s + 1) << 6);
        compute(s & 1);
        if (s + 1 < S) {
            stage_tile((s + 1) & 1);
            __syncthreads();
        }
    }

#pragma unroll
    for (int ma = 0; ma < 2; ma++) {
        int r0 = bm + wm + ma * 16 + (lane >> 2);
#pragma unroll
        for (int na = 0; na < 4; na++) {
            int c0 = bn + wn + na * 8 + ((lane & 3) << 1);
            float b0v = bias[c0], b1v = bias[c0 + 1];
            float v00 = acc[ma][na][0] + b0v, v01 = acc[ma][na][1] + b1v;
            float v10 = acc[ma][na][2] + b0v, v11 = acc[ma][na][3] + b1v;
            if (ACT == 1) {
                v00 = gelu_tanh(v00); v01 = gelu_tanh(v01);
                v10 = gelu_tanh(v10); v11 = gelu_tanh(v11);
            }
            if (RES) {
                v00 += res[(size_t)r0 * N + c0];
                v01 += res[(size_t)r0 * N + c0 + 1];
                v10 += res[(size_t)(r0 + 8) * N + c0];
                v11 += res[(size_t)(r0 + 8) * N + c0 + 1];
            }
            *reinterpret_cast<float2*>(&C[(size_t)r0 * N + c0]) = make_float2(v00, v01);
            *reinterpret_cast<float2*>(&C[(size_t)(r0 + 8) * N + c0]) = make_float2(v10, v11);
        }
    }
}

// ---------------------------------------------------------------------------
// Tensor-core flash attention (R16 verified, unchanged).
// ---------------------------------------------------------------------------
__global__ void __launch_bounds__(256, 2) attn_mma(
    const __nv_bfloat16* __restrict__ qkvh,
    const __nv_bfloat16* __restrict__ qkvl, float* __restrict__ out)
{
    extern __shared__ char asm_[];
    const unsigned sb = (unsigned)__cvta_generic_to_shared(asm_);

    const int b = blockIdx.y >> 4;
    const int h = blockIdx.y & 15;
    const int q0 = blockIdx.x * 128;
    const int tid = threadIdx.x;
    const int lane = tid & 31;
    const int warp = tid >> 5;
    const size_t rowbase = (size_t)b * T_ * QKVW;
    const int hc = h * 64;

#pragma unroll
    for (int i = 0; i < 8; i++) {
        int f = tid + 256 * i;
        int plane = f >> 10;
        int r = (f >> 3) & 127;
        int c = f & 7;
        const __nv_bfloat16* src =
            (plane ? qkvl : qkvh) + rowbase + (size_t)(q0 + r) * QKVW + hc + c * 8;
        unsigned dst = plane ? (sb + r * 144 + c * 16)
                             : (sb + AQLO + r * 144 + c * 16);
        cpa16(dst, src);
    }
    cpa_commit();
    cpa_wait<0>();
    __syncthreads();

    unsigned short* Ql = (unsigned short*)asm_;
    unsigned short* Qh = (unsigned short*)(asm_ + AQLO);
    unsigned qh[4][4];
#pragma unroll
    for (int ks = 0; ks < 4; ks++) {
        int row = warp * 16 + (lane & 15);
        int col = ks * 16 + ((lane >> 4) << 3);
        ldmx4(qh[ks], (unsigned)__cvta_generic_to_shared(&Qh[row * 72 + col]));
    }
    __syncthreads();

    float oacc[8][4];
#pragma unroll
    for (int t = 0; t < 8; t++)
#pragma unroll
        for (int j = 0; j < 4; j++) oacc[t][j] = 0.0f;
    float m0 = -1e30f, m1 = -1e30f, lsum0 = 0.0f, lsum1 = 0.0f;

    auto stage_kv = [&](int s) {
        int kt = s * 64;
        unsigned base = sb + AQLO + (s & 1) * ABUF;
#pragma unroll
        for (int i = 0; i < 8; i++) {
            int f = tid + 256 * i;
            int plane = f >> 9;
            int r = (f >> 3) & 63;
            int c = f & 7;
            int col = ((plane >> 1) ? 2 * E_ : E_) + hc + c * 8;
            const __nv_bfloat16* pl = (plane & 1) ? qkvl : qkvh;
            cpa16(base + plane * 9216 + r * 144 + c * 16,
                  pl + rowbase + (size_t)(kt + r) * QKVW + col);
        }
        cpa_commit();
    };

    stage_kv(0);
    stage_kv(1);

    constexpr int NIT = T_ / 64;
    for (int it = 0; it < NIT; it++) {
        cpa_wait<1>();
        __syncthreads();

        const int bb = it & 1;
        unsigned short* Kh = (unsigned short*)(asm_ + AQLO + bb * ABUF);
        unsigned short* Kl = Kh + 4608;
        unsigned short* Vh = Kh + 9216;
        unsigned short* Vl = Kh + 13824;

        float sacc[8][4];
#pragma unroll
        for (int t = 0; t < 8; t++)
#pragma unroll
            for (int j = 0; j < 4; j++) sacc[t][j] = 0.0f;

#pragma unroll
        for (int ks = 0; ks < 4; ks++) {
            unsigned qlr[4];
            {
                int row = warp * 16 + (lane & 15);
                int col = ks * 16 + ((lane >> 4) << 3);
                ldmx4(qlr, (unsigned)__cvta_generic_to_shared(&Ql[row * 72 + col]));
            }
#pragma unroll
            for (int g = 0; g < 4; g++) {
                int row = g * 16 + ((lane >> 4) << 3) + (lane & 7);
                int col = ks * 16 + (((lane >> 3) & 1) << 3);
                unsigned bh[4], bl[4];
                ldmx4(bh, (unsigned)__cvta_generic_to_shared(&Kh[row * 72 + col]));
                ldmx4(bl, (unsigned)__cvta_generic_to_shared(&Kl[row * 72 + col]));
                mma16816(sacc[2 * g],     qh[ks], &bh[0]);
                mma16816(sacc[2 * g],     qh[ks], &bl[0]);
                mma16816(sacc[2 * g],     qlr,    &bh[0]);
                mma16816(sacc[2 * g + 1], qh[ks], &bh[2]);
                mma16816(sacc[2 * g + 1], qh[ks], &bl[2]);
                mma16816(sacc[2 * g + 1], qlr,    &bh[2]);
            }
        }
#pragma unroll
        for (int t = 0; t < 8; t++) {
            sacc[t][0] *= 0.125f; sacc[t][1] *= 0.125f;
            sacc[t][2] *= 0.125f; sacc[t][3] *= 0.125f;
        }

        float mx0 = -1e30f, mx1 = -1e30f;
#pragma unroll
        for (int t = 0; t < 8; t++) {
            mx0 = fmaxf(mx0, fmaxf(sacc[t][0], sacc[t][1]));
            mx1 = fmaxf(mx1, fmaxf(sacc[t][2], sacc[t][3]));
        }
        mx0 = fmaxf(mx0, __shfl_xor_sync(0xffffffffu, mx0, 1));
        mx0 = fmaxf(mx0, __shfl_xor_sync(0xffffffffu, mx0, 2));
        mx1 = fmaxf(mx1, __shfl_xor_sync(0xffffffffu, mx1, 1));
        mx1 = fmaxf(mx1, __shfl_xor_sync(0xffffffffu, mx1, 2));
        float mn0 = fmaxf(m0, mx0), mn1 = fmaxf(m1, mx1);
        float c0 = __expf(m0 - mn0), c1 = __expf(m1 - mn1);
        m0 = mn0; m1 = mn1;
        float s0 = 0.0f, s1 = 0.0f;
#pragma unroll
        for (int t = 0; t < 8; t++) {
            sacc[t][0] = __expf(sacc[t][0] - m0);
            sacc[t][1] = __expf(sacc[t][1] - m0);
            sacc[t][2] = __expf(sacc[t][2] - m1);
            sacc[t][3] = __expf(sacc[t][3] - m1);
            s0 += sacc[t][0] + sacc[t][1];
            s1 += sacc[t][2] + sacc[t][3];
        }
        s0 += __shfl_xor_sync(0xffffffffu, s0, 1);
        s0 += __shfl_xor_sync(0xffffffffu, s0, 2);
        s1 += __shfl_xor_sync(0xffffffffu, s1, 1);
        s1 += __shfl_xor_sync(0xffffffffu, s1, 2);
        lsum0 = lsum0 * c0 + s0;
        lsum1 = lsum1 * c1 + s1;
#pragma unroll
        for (int t = 0; t < 8; t++) {
            oacc[t][0] *= c0; oacc[t][1] *= c0;
            oacc[t][2] *= c1; oacc[t][3] *= c1;
        }

#pragma unroll
        for (int kk = 0; kk < 4; kk++) {
            unsigned ph[4], pl[4];
            ph[0] = pack2(sacc[2 * kk][0], sacc[2 * kk][1]);
            ph[1] = pack2(sacc[2 * kk][2], sacc[2 * kk][3]);
            ph[2] = pack2(sacc[2 * kk + 1][0], sacc[2 * kk + 1][1]);
            ph[3] = pack2(sacc[2 * kk + 1][2], sacc[2 * kk + 1][3]);
#pragma unroll
            for (int u2 = 0; u2 < 4; u2++) {
                const float* p = sacc[2 * kk + (u2 >> 1)];
                int o = (u2 & 1) * 2;
                float rx = __uint_as_float(ph[u2] << 16);
                float ry = __uint_as_float(ph[u2] & 0xFFFF0000u);
                pl[u2] = pack2(p[o] - rx, p[o + 1] - ry);
            }
#pragma unroll
            for (int g = 0; g < 4; g++) {
                int row = kk * 16 + (((lane >> 3) & 1) << 3) + (lane & 7);
                int col = g * 16 + ((lane >> 4) << 3);
                unsigned vh[4], vl[4];
                ldmx4t(vh, (unsigned)__cvta_generic_to_shared(&Vh[row * 72 + col]));
                ldmx4t(vl, (unsigned)__cvta_generic_to_shared(&Vl[row * 72 + col]));
                mma16816(oacc[2 * g],     ph, &vh[0]);
                mma16816(oacc[2 * g],     ph, &vl[0]);
                mma16816(oacc[2 * g],     pl, &vh[0]);
                mma16816(oacc[2 * g + 1], ph, &vh[2]);
                mma16816(oacc[2 * g + 1], ph, &vl[2]);
                mma16816(oacc[2 * g + 1], pl, &vh[2]);
            }
        }

        if (it + 2 < NIT) {
            __syncthreads();
            stage_kv(it + 2);
        }
    }

    float inv0 = 1.0f / lsum0, inv1 = 1.0f / lsum1;
    int r0 = q0 + warp * 16 + (lane >> 2);
#pragma unroll
    for (int t = 0; t < 8; t++) {
        int col = hc + t * 8 + ((lane & 3) << 1);
        *reinterpret_cast<float2*>(&out[((size_t)b * T_ + r0) * E_ + col]) =
            make_float2(oacc[t][0] * inv0, oacc[t][1] * inv0);
        *reinterpret_cast<float2*>(&out[((size_t)b * T_ + r0 + 8) * E_ + col]) =
            make_float2(oacc[t][2] * inv1, oacc[t][3] * inv1);
    }
}

// ---------------------------------------------------------------------------
// Orchestration
// ---------------------------------------------------------------------------
extern "C" void kernel_launch(void* const* d_in, const int* in_sizes, int n_in,
                              void* d_out, int out_size)
{
    const float* x_in  = (const float*)d_in[0];
    const float* Wqkv  = (const float*)d_in[1];
    const float* bqkv  = (const float*)d_in[2];
    const float* Wproj = (const float*)d_in[3];
    const float* bproj = (const float*)d_in[4];
    const float* W1    = (const float*)d_in[5];
    const float* b1    = (const float*)d_in[6];
    const float* W2    = (const float*)d_in[7];
    const float* b2    = (const float*)d_in[8];
    float* out = (float*)d_out;

    cudaFuncSetAttribute(gemm_mma<0, false, true>,
                         cudaFuncAttributeMaxDynamicSharedMemorySize, SMEM_G);
    cudaFuncSetAttribute(gemm_mma<0, true, false>,
                         cudaFuncAttributeMaxDynamicSharedMemorySize, SMEM_G);
    cudaFuncSetAttribute(gemm_f16<1, false>,
                         cudaFuncAttributeMaxDynamicSharedMemorySize, SMEM_F);
    cudaFuncSetAttribute(gemm_f16<0, true>,
                         cudaFuncAttributeMaxDynamicSharedMemorySize, SMEM_F);
    cudaFuncSetAttribute(attn_mma,
                         cudaFuncAttributeMaxDynamicSharedMemorySize, SMEM_A);

    float *gx, *gattn, *gh;
    __nv_bfloat16 *gqh, *gql;
    cudaGetSymbolAddress((void**)&gx, g_x);
    cudaGetSymbolAddress((void**)&gattn, g_attn);
    cudaGetSymbolAddress((void**)&gh, g_h);
    cudaGetSymbolAddress((void**)&gqh, g_qkvh);
    cudaGetSymbolAddress((void**)&gql, g_qkvl);

    dim3 blk(512);
    for (int l = 0; l < L_; l++) {
        const float* xcur = (l == 0) ? x_in : gx;

        // QKV (bf16 3-term): writes hi/lo planes for attention
        gemm_mma<0, false, true><<<dim3(QKVW / 128, M_ / 128), blk, SMEM_G>>>(
            xcur, Wqkv + (size_t)l * E_ * QKVW, bqkv + (size_t)l * QKVW,
            nullptr, nullptr, gqh, gql, M_, QKVW, E_);

        attn_mma<<<dim3(T_ / 128, B_ * H_), 256, SMEM_A>>>(gqh, gql, gattn);

        // proj + residual (bf16 3-term)
        gemm_mma<0, true, false><<<dim3(E_ / 128, M_ / 128), blk, SMEM_G>>>(
            gattn, Wproj + (size_t)l * E_ * E_, bproj + (size_t)l * E_,
            xcur, gx, nullptr, nullptr, M_, E_, E_);

        // MLP up + GELU (fp16 2-term)
        gemm_f16<1, false><<<dim3(FFDIM / 128, M_ / 128), blk, SMEM_F>>>(
            gx, W1 + (size_t)l * E_ * FFDIM, b1 + (size_t)l * FFDIM,
            nullptr, gh, M_, FFDIM, E_);

        // MLP down + residual (fp16 2-term)
        float* dst = (l == L_ - 1) ? out : gx;
        gemm_f16<0, true><<<dim3(E_ / 128, M_ / 128), blk, SMEM_F>>>(
            gh, W2 + (size_t)l * FFDIM * E_, b2 + (size_t)l * E_,
            gx, dst, M_, E_, FFDIM);
    }
}